// round 3
// baseline (speedup 1.0000x reference)
#include <cuda_runtime.h>

#define D    128
#define TM   64
#define WPITCH 132
#define MAXN 50048
#define MAXE 1000000
#define NBLK ((MAXN + 255) / 256)

// ---- scratch (no allocations allowed) ----
__device__ float g_dinv[MAXN];
__device__ int   g_deg[MAXN];
__device__ int   g_rowptr[MAXN];
__device__ int   g_cursor[MAXN];
__device__ int   g_csr[MAXE];
__device__ float g_h[(size_t)MAXN * D];        // pre-scaled GEMM output hs = (X@W)*dinv[row]
__device__ float g_agg[(size_t)MAXN * D];      // conv1 final output / BN input
__device__ float g_bnsums[2 * D];
__device__ int   g_bsum[NBLK];

// ---------------- packed f32x2 helpers ----------------
__device__ __forceinline__ void upk2(unsigned long long v, float& lo, float& hi) {
    asm("mov.b64 {%0, %1}, %2;" : "=f"(lo), "=f"(hi) : "l"(v));
}
#define FFMA2(d, a, b) asm("fma.rn.f32x2 %0, %1, %2, %0;" : "+l"(d) : "l"(a), "l"(b))

// ---------------- init: zero deg + BN accumulators ----------------
__global__ void init_kernel(int n) {
    int i = blockIdx.x * blockDim.x + threadIdx.x;
    if (i < n) g_deg[i] = 0;
    if (i < 2 * D) g_bnsums[i] = 0.0f;
}

// ---------------- degree histogram over edge destinations ----------------
__global__ void deg_kernel(const int* __restrict__ dst, int E) {
    int e = blockIdx.x * blockDim.x + threadIdx.x;
    if (e < E) atomicAdd(&g_deg[dst[e]], 1);
}

// ---------------- block-level exclusive scan helpers ----------------
__device__ __forceinline__ int block_scan_excl(int v, int& total) {
    __shared__ int ws[8];
    int lane = threadIdx.x & 31, wid = threadIdx.x >> 5;
    int x = v;
#pragma unroll
    for (int o = 1; o < 32; o <<= 1) {
        int y = __shfl_up_sync(0xffffffffu, x, o);
        if (lane >= o) x += y;
    }
    if (lane == 31) ws[wid] = x;
    __syncthreads();
    if (wid == 0) {
        int t = (lane < 8) ? ws[lane] : 0;
#pragma unroll
        for (int o = 1; o < 8; o <<= 1) {
            int y = __shfl_up_sync(0xffffffffu, t, o);
            if (lane >= o) t += y;
        }
        if (lane < 8) ws[lane] = t;
    }
    __syncthreads();
    int incl = x + (wid > 0 ? ws[wid - 1] : 0);
    total = ws[7];
    return incl - v;
}

__global__ void scanA_kernel(int n) {
    int i = blockIdx.x * 256 + threadIdx.x;
    int v = (i < n) ? g_deg[i] : 0;
    int total;
    int excl = block_scan_excl(v, total);
    if (i < n) g_rowptr[i] = excl;
    if (threadIdx.x == 0) g_bsum[blockIdx.x] = total;
}

__global__ void scanB_kernel(int nb) {
    int i = threadIdx.x;
    int v = (i < nb) ? g_bsum[i] : 0;
    int total;
    int excl = block_scan_excl(v, total);
    if (i < nb) g_bsum[i] = excl;
}

__global__ void scanC_kernel(int n) {
    int i = blockIdx.x * 256 + threadIdx.x;
    if (i < n) {
        int rp = g_rowptr[i] + g_bsum[blockIdx.x];
        g_rowptr[i] = rp;
        g_cursor[i] = rp;
        g_dinv[i] = rsqrtf(1.0f + (float)g_deg[i]);
    }
}

// ---------------- bucket fill: csr[dst buckets] = src ----------------
__global__ void fill_kernel(const int* __restrict__ src, const int* __restrict__ dst, int E) {
    int e = blockIdx.x * blockDim.x + threadIdx.x;
    if (e < E) {
        int pos = atomicAdd(&g_cursor[dst[e]], 1);
        g_csr[pos] = src[e];
    }
}

// ---------------- GEMM: Hout = (X @ W) * dinv[row]  (BN+ReLU on X if asked)
// k-packed f32x2: acc.lo accumulates even k, acc.hi odd k; zero packing MOVs.
// A from row-major Xs (LDS.128 = 4 consecutive k, warp-broadcast).
// B from transposed Ws (pitch 132; column-stride-32 lane map -> conflict-free).
__global__ __launch_bounds__(256) void gemm_kernel(
    const float* __restrict__ X, const float* __restrict__ W,
    float* __restrict__ Hout, int n, int use_bn,
    const float* __restrict__ gamma, const float* __restrict__ beta,
    float invN)
{
    extern __shared__ float sm[];
    float* Wt      = sm;                    // 128 x 132
    float* Xs      = sm + D * WPITCH;       // 64 x 128
    float* scale_s = Xs + TM * D;           // 128
    float* shift_s = scale_s + D;           // 128

    int tid  = threadIdx.x;
    int lane = tid & 31;
    int wrp  = tid >> 5;

    if (use_bn && tid < D) {
        float mu  = g_bnsums[tid] * invN;
        float var = g_bnsums[D + tid] * invN - mu * mu;
        float sc  = gamma[tid] * rsqrtf(var + 1e-5f);
        scale_s[tid] = sc;
        shift_s[tid] = beta[tid] - mu * sc;
    }

    // stage W transposed: Wt[c * 132 + k] = W[k][c]
    // lane -> k (conflict-free STS; strided global read stays in L2, W is hot)
#pragma unroll
    for (int iter = 0; iter < 16; iter++) {
        int ki = iter >> 2, cb = iter & 3;
        int k  = ki * 32 + lane;
        int c0 = (cb * 8 + wrp) * 4;
        float4 v = ((const float4*)W)[k * 32 + (c0 >> 2)];
        Wt[(c0 + 0) * WPITCH + k] = v.x;
        Wt[(c0 + 1) * WPITCH + k] = v.y;
        Wt[(c0 + 2) * WPITCH + k] = v.z;
        Wt[(c0 + 3) * WPITCH + k] = v.w;
    }
    __syncthreads();

    // stage X tile (BN+ReLU applied on load if asked)
    int row0 = blockIdx.x * TM;
    float4* Xs4w = (float4*)Xs;
#pragma unroll
    for (int i = 0; i < 8; i++) {
        int idx = tid + i * 256;
        int r   = idx >> 5;
        int c4  = idx & 31;
        int grow = row0 + r;
        float4 v = make_float4(0.f, 0.f, 0.f, 0.f);
        if (grow < n) v = ((const float4*)X)[(size_t)grow * 32 + c4];
        if (use_bn) {
            int f = c4 * 4;
            v.x = fmaxf(0.f, fmaf(v.x, scale_s[f + 0], shift_s[f + 0]));
            v.y = fmaxf(0.f, fmaf(v.y, scale_s[f + 1], shift_s[f + 1]));
            v.z = fmaxf(0.f, fmaf(v.z, scale_s[f + 2], shift_s[f + 2]));
            v.w = fmaxf(0.f, fmaf(v.w, scale_s[f + 3], shift_s[f + 3]));
        }
        Xs4w[idx] = v;
    }
    __syncthreads();

    const float4* Xs4 = (const float4*)Xs;

    // thread tile: 8 rows (wrp*8..+7) x 4 cols (lane + 32g)
    unsigned long long acc[8][4];
#pragma unroll
    for (int r = 0; r < 8; r++)
#pragma unroll
        for (int g = 0; g < 4; g++) acc[r][g] = 0ull;

#pragma unroll 4
    for (int k4 = 0; k4 < 32; k4++) {
        float4 bf[4];
#pragma unroll
        for (int g = 0; g < 4; g++)
            bf[g] = *(const float4*)&Wt[(g * 32 + lane) * WPITCH + k4 * 4];
#pragma unroll
        for (int r = 0; r < 8; r++) {
            float4 af = Xs4[(wrp * 8 + r) * 32 + k4];   // warp broadcast
            ulonglong2 a = *reinterpret_cast<ulonglong2*>(&af);
#pragma unroll
            for (int g = 0; g < 4; g++) {
                ulonglong2 b = *reinterpret_cast<ulonglong2*>(&bf[g]);
                FFMA2(acc[r][g], a.x, b.x);
                FFMA2(acc[r][g], a.y, b.y);
            }
        }
    }

#pragma unroll
    for (int r = 0; r < 8; r++) {
        int row = row0 + wrp * 8 + r;
        if (row >= n) continue;
        float dv = g_dinv[row];
#pragma unroll
        for (int g = 0; g < 4; g++) {
            float lo, hi;
            upk2(acc[r][g], lo, hi);
            Hout[(size_t)row * D + g * 32 + lane] = (lo + hi) * dv;
        }
    }
}

// ---------------- CSR scatter: out[d] = (hs[d] + sum_{s in N(d)} hs[s]) * dinv[d] + bias
// One warp per node. BN_STATS variant also accumulates per-feature sum/sumsq.
template <int BN_STATS>
__global__ __launch_bounds__(256) void scatter_csr_kernel(
    const float* __restrict__ hs, float* __restrict__ out,
    const float* __restrict__ bias, int n)
{
    __shared__ float sred[BN_STATS ? 8 * D : 1];
    int wrp  = threadIdx.x >> 5;
    int lane = threadIdx.x & 31;
    int node = blockIdx.x * 8 + wrp;
    float4 o = make_float4(0.f, 0.f, 0.f, 0.f);

    if (node < n) {
        size_t base = (size_t)node * D + lane * 4;
        float4 acc = *(const float4*)(hs + base);   // self loop
        int start = g_rowptr[node];
        int cnt   = g_deg[node];
        int j = 0;
        for (; j + 4 <= cnt; j += 4) {
            int s0 = __ldg(&g_csr[start + j + 0]);
            int s1 = __ldg(&g_csr[start + j + 1]);
            int s2 = __ldg(&g_csr[start + j + 2]);
            int s3 = __ldg(&g_csr[start + j + 3]);
            float4 v0 = *(const float4*)(hs + (size_t)s0 * D + lane * 4);
            float4 v1 = *(const float4*)(hs + (size_t)s1 * D + lane * 4);
            float4 v2 = *(const float4*)(hs + (size_t)s2 * D + lane * 4);
            float4 v3 = *(const float4*)(hs + (size_t)s3 * D + lane * 4);
            acc.x += (v0.x + v1.x) + (v2.x + v3.x);
            acc.y += (v0.y + v1.y) + (v2.y + v3.y);
            acc.z += (v0.z + v1.z) + (v2.z + v3.z);
            acc.w += (v0.w + v1.w) + (v2.w + v3.w);
        }
        for (; j < cnt; j++) {
            int s = __ldg(&g_csr[start + j]);
            float4 v = *(const float4*)(hs + (size_t)s * D + lane * 4);
            acc.x += v.x; acc.y += v.y; acc.z += v.z; acc.w += v.w;
        }
        float dv = g_dinv[node];
        float4 bv = ((const float4*)bias)[lane];
        o.x = fmaf(acc.x, dv, bv.x);
        o.y = fmaf(acc.y, dv, bv.y);
        o.z = fmaf(acc.z, dv, bv.z);
        o.w = fmaf(acc.w, dv, bv.w);
        *(float4*)(out + base) = o;
    }

    if (BN_STATS) {
        *(float4*)&sred[wrp * D + lane * 4] = o;   // zeros for invalid nodes
        __syncthreads();
        if (threadIdx.x < D) {
            float s = 0.f, s2 = 0.f;
#pragma unroll
            for (int w = 0; w < 8; w++) {
                float v = sred[w * D + threadIdx.x];
                s += v;
                s2 = fmaf(v, v, s2);
            }
            atomicAdd(&g_bnsums[threadIdx.x], s);
            atomicAdd(&g_bnsums[D + threadIdx.x], s2);
        }
    }
}

extern "C" void kernel_launch(void* const* d_in, const int* in_sizes, int n_in,
                              void* d_out, int out_size)
{
    const float* x     = (const float*)d_in[0];
    const int*   ei    = (const int*)  d_in[1];
    const float* W1    = (const float*)d_in[2];
    const float* b1    = (const float*)d_in[3];
    const float* gamma = (const float*)d_in[4];
    const float* beta  = (const float*)d_in[5];
    const float* W2    = (const float*)d_in[6];
    const float* b2    = (const float*)d_in[7];
    float* out = (float*)d_out;

    int n = in_sizes[0] / D;
    int E = in_sizes[1] / 2;
    const int* src = ei;
    const int* dst = ei + E;
    float invN = 1.0f / (float)n;

    int smem = (D * WPITCH + TM * D + 2 * D) * (int)sizeof(float);  // 101376 B
    cudaFuncSetAttribute(gemm_kernel,
                         cudaFuncAttributeMaxDynamicSharedMemorySize, smem);

    void* p;
    cudaGetSymbolAddress(&p, g_h);   float* hbuf   = (float*)p;
    cudaGetSymbolAddress(&p, g_agg); float* aggbuf = (float*)p;

    int nb = (n + 255) / 256;

    init_kernel<<<nb, 256>>>(n);
    deg_kernel<<<(E + 255) / 256, 256>>>(dst, E);
    scanA_kernel<<<nb, 256>>>(n);
    scanB_kernel<<<1, 256>>>(nb);
    scanC_kernel<<<nb, 256>>>(n);
    fill_kernel<<<(E + 255) / 256, 256>>>(src, dst, E);

    int gblocks = (n + TM - 1) / TM;
    int sblocks = (n + 7) / 8;

    // conv1 (+ fused BN statistics in the scatter epilogue)
    gemm_kernel<<<gblocks, 256, smem>>>(x, W1, hbuf, n, 0, nullptr, nullptr, invN);
    scatter_csr_kernel<1><<<sblocks, 256>>>(hbuf, aggbuf, b1, n);

    // conv2 (BN+ReLU fused into X load)
    gemm_kernel<<<gblocks, 256, smem>>>(aggbuf, W2, hbuf, n, 1, gamma, beta, invN);
    scatter_csr_kernel<0><<<sblocks, 256>>>(hbuf, out, b2, n);
}

// round 4
// speedup vs baseline: 1.1019x; 1.1019x over previous
#include <cuda_runtime.h>

#define D    128
#define TM   64
#define MAXN 50048
#define MAXE 1000000

// ---- scratch (zero-initialized at module load; re-zeroed by scatter2 epilogue) ----
__device__ float g_dinv[MAXN];
__device__ int   g_deg[MAXN];       // must be 0 at start of every replay
__device__ int   g_rowptr[MAXN];
__device__ int   g_cursor[MAXN];
__device__ int   g_csr[MAXE];
__device__ float g_h[(size_t)MAXN * D];
__device__ float g_agg[(size_t)MAXN * D];
__device__ float g_bnsums[2 * D];   // must be 0 at start of every replay
__device__ int   g_total;           // must be 0 at start of every replay

// ---------------- packed f32x2 helpers ----------------
__device__ __forceinline__ unsigned long long pk2(float lo, float hi) {
    unsigned long long r;
    asm("mov.b64 %0, {%1, %2};" : "=l"(r) : "f"(lo), "f"(hi));
    return r;
}
__device__ __forceinline__ void upk2(unsigned long long v, float& lo, float& hi) {
    asm("mov.b64 {%0, %1}, %2;" : "=f"(lo), "=f"(hi) : "l"(v));
}
#define FFMA2(d, a, b) asm("fma.rn.f32x2 %0, %1, %2, %0;" : "+l"(d) : "l"(a), "l"(b))

// ---------------- degree histogram over edge destinations ----------------
__global__ void deg_kernel(const int* __restrict__ dst, int E) {
    int e = blockIdx.x * blockDim.x + threadIdx.x;
    if (e < E) atomicAdd(&g_deg[dst[e]], 1);
}

// ---------------- bucket allocation (order-free CSR offsets) + dinv ----------------
__global__ void alloc_kernel(int n) {
    int i = blockIdx.x * blockDim.x + threadIdx.x;
    if (i < n) {
        int dg = g_deg[i];
        int rp = atomicAdd(&g_total, dg);   // warp-aggregated by compiler
        g_rowptr[i] = rp;
        g_cursor[i] = rp;
        g_dinv[i] = rsqrtf(1.0f + (float)dg);
    }
}

// ---------------- bucket fill: csr[dst buckets] = src ----------------
__global__ void fill_kernel(const int* __restrict__ src, const int* __restrict__ dst, int E) {
    int e = blockIdx.x * blockDim.x + threadIdx.x;
    if (e < E) {
        int pos = atomicAdd(&g_cursor[dst[e]], 1);
        g_csr[pos] = src[e];
    }
}

// ---------------- GEMM: Hout = (X @ W) * dinv[row]  (BN+ReLU on X if asked)
__global__ __launch_bounds__(256, 2) void gemm_kernel(
    const float* __restrict__ X, const float* __restrict__ W,
    float* __restrict__ Hout, int n, int use_bn,
    const float* __restrict__ gamma, const float* __restrict__ beta,
    float invN)
{
    extern __shared__ float sm[];
    float* Ws      = sm;                 // 128*128
    float* Xs      = sm + D * D;         // 64*128
    float* scale_s = Xs + TM * D;        // 128
    float* shift_s = scale_s + D;        // 128

    int tid = threadIdx.x;
    int tx = tid & 31;      // column group (4 cols)
    int ty = tid >> 5;      // row group (8 rows)

    if (use_bn && tid < D) {
        float mu  = g_bnsums[tid] * invN;
        float var = g_bnsums[D + tid] * invN - mu * mu;
        float sc  = gamma[tid] * rsqrtf(var + 1e-5f);
        scale_s[tid] = sc;
        shift_s[tid] = beta[tid] - mu * sc;
    }

    const float4* W4 = (const float4*)W;
    float4* Ws4w = (float4*)Ws;
#pragma unroll
    for (int i = 0; i < 16; i++) Ws4w[tid + i * 256] = W4[tid + i * 256];
    __syncthreads();

    int row0 = blockIdx.x * TM;
    float4* Xs4w = (float4*)Xs;
#pragma unroll
    for (int i = 0; i < 8; i++) {
        int idx = tid + i * 256;
        int r   = idx >> 5;
        int c4  = idx & 31;
        int grow = row0 + r;
        float4 v = make_float4(0.f, 0.f, 0.f, 0.f);
        if (grow < n) v = ((const float4*)X)[(size_t)grow * 32 + c4];
        if (use_bn) {
            int f = c4 * 4;
            v.x = fmaxf(0.f, fmaf(v.x, scale_s[f + 0], shift_s[f + 0]));
            v.y = fmaxf(0.f, fmaf(v.y, scale_s[f + 1], shift_s[f + 1]));
            v.z = fmaxf(0.f, fmaf(v.z, scale_s[f + 2], shift_s[f + 2]));
            v.w = fmaxf(0.f, fmaf(v.w, scale_s[f + 3], shift_s[f + 3]));
        }
        Xs4w[idx] = v;
    }
    __syncthreads();

    const float4* Ws4 = (const float4*)Ws;
    const float4* Xs4 = (const float4*)Xs;

    // acc[rp][c] holds packed rows (2rp, 2rp+1) for output column tx*4+c
    unsigned long long acc[4][4];
#pragma unroll
    for (int rp = 0; rp < 4; rp++)
#pragma unroll
        for (int c = 0; c < 4; c++) acc[rp][c] = 0ull;

#pragma unroll 4
    for (int k4 = 0; k4 < 32; k4++) {
        float4 b0 = Ws4[(k4 * 4 + 0) * 32 + tx];
        float4 b1 = Ws4[(k4 * 4 + 1) * 32 + tx];
        float4 b2 = Ws4[(k4 * 4 + 2) * 32 + tx];
        float4 b3 = Ws4[(k4 * 4 + 3) * 32 + tx];
        unsigned long long bb0[4] = {pk2(b0.x,b0.x), pk2(b1.x,b1.x), pk2(b2.x,b2.x), pk2(b3.x,b3.x)};
        unsigned long long bb1[4] = {pk2(b0.y,b0.y), pk2(b1.y,b1.y), pk2(b2.y,b2.y), pk2(b3.y,b3.y)};
        unsigned long long bb2[4] = {pk2(b0.z,b0.z), pk2(b1.z,b1.z), pk2(b2.z,b2.z), pk2(b3.z,b3.z)};
        unsigned long long bb3[4] = {pk2(b0.w,b0.w), pk2(b1.w,b1.w), pk2(b2.w,b2.w), pk2(b3.w,b3.w)};
#pragma unroll
        for (int rp = 0; rp < 4; rp++) {
            float4 a0 = Xs4[(ty * 8 + rp * 2 + 0) * 32 + k4];
            float4 a1 = Xs4[(ty * 8 + rp * 2 + 1) * 32 + k4];
            unsigned long long ax = pk2(a0.x, a1.x);
            unsigned long long ay = pk2(a0.y, a1.y);
            unsigned long long az = pk2(a0.z, a1.z);
            unsigned long long aw = pk2(a0.w, a1.w);
            FFMA2(acc[rp][0], ax, bb0[0]); FFMA2(acc[rp][0], ay, bb0[1]);
            FFMA2(acc[rp][0], az, bb0[2]); FFMA2(acc[rp][0], aw, bb0[3]);
            FFMA2(acc[rp][1], ax, bb1[0]); FFMA2(acc[rp][1], ay, bb1[1]);
            FFMA2(acc[rp][1], az, bb1[2]); FFMA2(acc[rp][1], aw, bb1[3]);
            FFMA2(acc[rp][2], ax, bb2[0]); FFMA2(acc[rp][2], ay, bb2[1]);
            FFMA2(acc[rp][2], az, bb2[2]); FFMA2(acc[rp][2], aw, bb2[3]);
            FFMA2(acc[rp][3], ax, bb3[0]); FFMA2(acc[rp][3], ay, bb3[1]);
            FFMA2(acc[rp][3], az, bb3[2]); FFMA2(acc[rp][3], aw, bb3[3]);
        }
    }

#pragma unroll
    for (int rp = 0; rp < 4; rp++) {
        int r0 = row0 + ty * 8 + rp * 2;
        int r1 = r0 + 1;
        float4 h0, h1;
        upk2(acc[rp][0], h0.x, h1.x);
        upk2(acc[rp][1], h0.y, h1.y);
        upk2(acc[rp][2], h0.z, h1.z);
        upk2(acc[rp][3], h0.w, h1.w);
        if (r0 < n) {
            float dv = g_dinv[r0];
            h0.x *= dv; h0.y *= dv; h0.z *= dv; h0.w *= dv;
            *(float4*)(Hout + (size_t)r0 * D + tx * 4) = h0;
        }
        if (r1 < n) {
            float dv = g_dinv[r1];
            h1.x *= dv; h1.y *= dv; h1.z *= dv; h1.w *= dv;
            *(float4*)(Hout + (size_t)r1 * D + tx * 4) = h1;
        }
    }
}

// ---------------- CSR scatter: out[d] = (hs[d] + sum_{s in N(d)} hs[s]) * dinv[d] + bias
// One warp per node. BN_STATS: accumulate per-feature sum/sumsq.
// CLEANUP: re-zero scratch state for the next graph replay.
template <int BN_STATS, int CLEANUP>
__global__ __launch_bounds__(256) void scatter_csr_kernel(
    const float* __restrict__ hs, float* __restrict__ out,
    const float* __restrict__ bias, int n)
{
    __shared__ float sred[BN_STATS ? 8 * D : 1];
    int wrp  = threadIdx.x >> 5;
    int lane = threadIdx.x & 31;
    int node = blockIdx.x * 8 + wrp;
    float4 o = make_float4(0.f, 0.f, 0.f, 0.f);

    if (node < n) {
        size_t base = (size_t)node * D + lane * 4;
        float4 acc = *(const float4*)(hs + base);   // self loop
        int start = g_rowptr[node];
        int cnt   = g_deg[node];
        int j = 0;
        for (; j + 8 <= cnt; j += 8) {
            int sidx[8];
#pragma unroll
            for (int u = 0; u < 8; u++) sidx[u] = __ldg(&g_csr[start + j + u]);
            float4 v[8];
#pragma unroll
            for (int u = 0; u < 8; u++)
                v[u] = *(const float4*)(hs + (size_t)sidx[u] * D + lane * 4);
#pragma unroll
            for (int u = 0; u < 8; u++) {
                acc.x += v[u].x; acc.y += v[u].y;
                acc.z += v[u].z; acc.w += v[u].w;
            }
        }
        for (; j < cnt; j++) {
            int s = __ldg(&g_csr[start + j]);
            float4 v = *(const float4*)(hs + (size_t)s * D + lane * 4);
            acc.x += v.x; acc.y += v.y; acc.z += v.z; acc.w += v.w;
        }
        float dv = g_dinv[node];
        float4 bv = ((const float4*)bias)[lane];
        o.x = fmaf(acc.x, dv, bv.x);
        o.y = fmaf(acc.y, dv, bv.y);
        o.z = fmaf(acc.z, dv, bv.z);
        o.w = fmaf(acc.w, dv, bv.w);
        *(float4*)(out + base) = o;
    }

    if (BN_STATS) {
        *(float4*)&sred[wrp * D + lane * 4] = o;   // zeros for invalid nodes
        __syncthreads();
        if (threadIdx.x < D) {
            float s = 0.f, s2 = 0.f;
#pragma unroll
            for (int w = 0; w < 8; w++) {
                float v = sred[w * D + threadIdx.x];
                s += v;
                s2 = fmaf(v, v, s2);
            }
            atomicAdd(&g_bnsums[threadIdx.x], s);
            atomicAdd(&g_bnsums[D + threadIdx.x], s2);
        }
    }

    if (CLEANUP) {
        // reset scratch so the next graph replay starts from a clean state
        if (node < n && lane == 0) g_deg[node] = 0;
        if (blockIdx.x == 0) {
            if (threadIdx.x < 2 * D) g_bnsums[threadIdx.x] = 0.0f;
            if (threadIdx.x == 0) g_total = 0;
        }
    }
}

extern "C" void kernel_launch(void* const* d_in, const int* in_sizes, int n_in,
                              void* d_out, int out_size)
{
    const float* x     = (const float*)d_in[0];
    const int*   ei    = (const int*)  d_in[1];
    const float* W1    = (const float*)d_in[2];
    const float* b1    = (const float*)d_in[3];
    const float* gamma = (const float*)d_in[4];
    const float* beta  = (const float*)d_in[5];
    const float* W2    = (const float*)d_in[6];
    const float* b2    = (const float*)d_in[7];
    float* out = (float*)d_out;

    int n = in_sizes[0] / D;
    int E = in_sizes[1] / 2;
    const int* src = ei;
    const int* dst = ei + E;
    float invN = 1.0f / (float)n;

    int smem = (D * D + TM * D + 2 * D) * (int)sizeof(float);  // 99328 B
    cudaFuncSetAttribute(gemm_kernel,
                         cudaFuncAttributeMaxDynamicSharedMemorySize, smem);

    void* p;
    cudaGetSymbolAddress(&p, g_h);   float* hbuf   = (float*)p;
    cudaGetSymbolAddress(&p, g_agg); float* aggbuf = (float*)p;

    int nb = (n + 255) / 256;
    int gblocks = (n + TM - 1) / TM;
    int sblocks = (n + 7) / 8;

    // prep: degrees -> bucket offsets -> bucket fill (g_deg/g_total zeroed by
    // module load on first call, and by scatter2's CLEANUP on every replay)
    deg_kernel<<<(E + 255) / 256, 256>>>(dst, E);
    alloc_kernel<<<nb, 256>>>(n);
    fill_kernel<<<(E + 255) / 256, 256>>>(src, dst, E);

    // conv1 (+ fused BN statistics in the scatter epilogue)
    gemm_kernel<<<gblocks, 256, smem>>>(x, W1, hbuf, n, 0, nullptr, nullptr, invN);
    scatter_csr_kernel<1, 0><<<sblocks, 256>>>(hbuf, aggbuf, b1, n);

    // conv2 (BN+ReLU fused into X load; cleanup fused into scatter epilogue)
    gemm_kernel<<<gblocks, 256, smem>>>(aggbuf, W2, hbuf, n, 1, gamma, beta, invN);
    scatter_csr_kernel<0, 1><<<sblocks, 256>>>(hbuf, out, b2, n);
}

// round 5
// speedup vs baseline: 1.2830x; 1.1643x over previous
#include <cuda_runtime.h>

#define D    128
#define TM   64
#define MAXN 50048
#define MAXE 1000000

// ---- scratch (zero-initialized at module load; re-zeroed by scatter2 epilogue) ----
__device__ float g_dinv[MAXN];
__device__ int   g_deg[MAXN];       // must be 0 at start of every replay
__device__ int   g_rowptr[MAXN];
__device__ int   g_cursor[MAXN];
__device__ int   g_csr[MAXE];
__device__ float g_h[(size_t)MAXN * D];
__device__ float g_agg[(size_t)MAXN * D];
__device__ float g_bnsums[2 * D];   // must be 0 at start of every replay
__device__ int   g_total;           // must be 0 at start of every replay

// ---------------- degree histogram over edge destinations ----------------
__global__ void deg_kernel(const int* __restrict__ dst, int E) {
    int e = blockIdx.x * blockDim.x + threadIdx.x;
    if (e < E) atomicAdd(&g_deg[dst[e]], 1);
}

// ---------------- bucket allocation (order-free CSR offsets) + dinv ----------------
__global__ void alloc_kernel(int n) {
    int i = blockIdx.x * blockDim.x + threadIdx.x;
    if (i < n) {
        int dg = g_deg[i];
        int rp = atomicAdd(&g_total, dg);   // warp-aggregated by compiler
        g_rowptr[i] = rp;
        g_cursor[i] = rp;
        g_dinv[i] = rsqrtf(1.0f + (float)dg);
    }
}

// ---------------- bucket fill: csr[dst buckets] = src ----------------
__global__ void fill_kernel(const int* __restrict__ src, const int* __restrict__ dst, int E) {
    int e = blockIdx.x * blockDim.x + threadIdx.x;
    if (e < E) {
        int pos = atomicAdd(&g_cursor[dst[e]], 1);
        g_csr[pos] = src[e];
    }
}

// ---------------- GEMM: Hout = (X @ W) * dinv[row]  (BN+ReLU on X if asked)
// Simple FFMA inner loop (measured: 51.6us, fma 40.5%, issue 59%)
__global__ __launch_bounds__(256) void gemm_kernel(
    const float* __restrict__ X, const float* __restrict__ W,
    float* __restrict__ Hout, int n, int use_bn,
    const float* __restrict__ gamma, const float* __restrict__ beta,
    float invN)
{
    extern __shared__ float sm[];
    float* Ws      = sm;                 // 128*128
    float* Xs      = sm + D * D;         // 64*128
    float* scale_s = Xs + TM * D;        // 128
    float* shift_s = scale_s + D;        // 128

    int tid = threadIdx.x;
    int tx = tid & 31;      // column group (4 cols)
    int ty = tid >> 5;      // row group (8 rows)

    if (use_bn && tid < D) {
        float mu  = g_bnsums[tid] * invN;
        float var = g_bnsums[D + tid] * invN - mu * mu;
        float sc  = gamma[tid] * rsqrtf(var + 1e-5f);
        scale_s[tid] = sc;
        shift_s[tid] = beta[tid] - mu * sc;
    }

    const float4* W4 = (const float4*)W;
    float4* Ws4 = (float4*)Ws;
#pragma unroll
    for (int i = 0; i < 16; i++) Ws4[tid + i * 256] = W4[tid + i * 256];
    __syncthreads();

    int row0 = blockIdx.x * TM;
    float4* Xs4 = (float4*)Xs;
#pragma unroll
    for (int i = 0; i < 8; i++) {
        int idx = tid + i * 256;
        int r   = idx >> 5;
        int c4  = idx & 31;
        int grow = row0 + r;
        float4 v = make_float4(0.f, 0.f, 0.f, 0.f);
        if (grow < n) v = ((const float4*)X)[(size_t)grow * 32 + c4];
        if (use_bn) {
            int f = c4 * 4;
            v.x = fmaxf(0.f, fmaf(v.x, scale_s[f + 0], shift_s[f + 0]));
            v.y = fmaxf(0.f, fmaf(v.y, scale_s[f + 1], shift_s[f + 1]));
            v.z = fmaxf(0.f, fmaf(v.z, scale_s[f + 2], shift_s[f + 2]));
            v.w = fmaxf(0.f, fmaf(v.w, scale_s[f + 3], shift_s[f + 3]));
        }
        Xs4[idx] = v;
    }
    __syncthreads();

    float acc[8][4];
#pragma unroll
    for (int r = 0; r < 8; r++)
#pragma unroll
        for (int c = 0; c < 4; c++) acc[r][c] = 0.f;

#pragma unroll 4
    for (int k = 0; k < D; k++) {
        float4 b = ((const float4*)(Ws + k * D))[tx];
#pragma unroll
        for (int r = 0; r < 8; r++) {
            float a = Xs[(ty * 8 + r) * D + k];   // warp broadcast
            acc[r][0] = fmaf(a, b.x, acc[r][0]);
            acc[r][1] = fmaf(a, b.y, acc[r][1]);
            acc[r][2] = fmaf(a, b.z, acc[r][2]);
            acc[r][3] = fmaf(a, b.w, acc[r][3]);
        }
    }

#pragma unroll
    for (int r = 0; r < 8; r++) {
        int grow = row0 + ty * 8 + r;
        if (grow >= n) continue;
        float dv = g_dinv[grow];
        float4 h = make_float4(acc[r][0] * dv, acc[r][1] * dv,
                               acc[r][2] * dv, acc[r][3] * dv);
        *(float4*)(Hout + (size_t)grow * D + tx * 4) = h;
    }
}

// ---------------- CSR scatter: out[d] = (hs[d] + sum_{s in N(d)} hs[s]) * dinv[d] + bias
// One warp per node, unroll-4, no block coupling.
// CLEANUP: re-zero scratch state for the next graph replay (independent writes).
template <int CLEANUP>
__global__ __launch_bounds__(256) void scatter_csr_kernel(
    const float* __restrict__ hs, float* __restrict__ out,
    const float* __restrict__ bias, int n)
{
    int node = (blockIdx.x * blockDim.x + threadIdx.x) >> 5;
    int lane = threadIdx.x & 31;
    if (node < n) {
        size_t base = (size_t)node * D + lane * 4;
        float4 acc = *(const float4*)(hs + base);   // self loop
        int start = g_rowptr[node];
        int cnt   = g_deg[node];
        int j = 0;
        for (; j + 4 <= cnt; j += 4) {
            int s0 = __ldg(&g_csr[start + j + 0]);
            int s1 = __ldg(&g_csr[start + j + 1]);
            int s2 = __ldg(&g_csr[start + j + 2]);
            int s3 = __ldg(&g_csr[start + j + 3]);
            float4 v0 = *(const float4*)(hs + (size_t)s0 * D + lane * 4);
            float4 v1 = *(const float4*)(hs + (size_t)s1 * D + lane * 4);
            float4 v2 = *(const float4*)(hs + (size_t)s2 * D + lane * 4);
            float4 v3 = *(const float4*)(hs + (size_t)s3 * D + lane * 4);
            acc.x += (v0.x + v1.x) + (v2.x + v3.x);
            acc.y += (v0.y + v1.y) + (v2.y + v3.y);
            acc.z += (v0.z + v1.z) + (v2.z + v3.z);
            acc.w += (v0.w + v1.w) + (v2.w + v3.w);
        }
        for (; j < cnt; j++) {
            int s = __ldg(&g_csr[start + j]);
            float4 v = *(const float4*)(hs + (size_t)s * D + lane * 4);
            acc.x += v.x; acc.y += v.y; acc.z += v.z; acc.w += v.w;
        }
        float dv = g_dinv[node];
        float4 bv = ((const float4*)bias)[lane];
        float4 o;
        o.x = fmaf(acc.x, dv, bv.x);
        o.y = fmaf(acc.y, dv, bv.y);
        o.z = fmaf(acc.z, dv, bv.z);
        o.w = fmaf(acc.w, dv, bv.w);
        *(float4*)(out + base) = o;

        if (CLEANUP && lane == 0) g_deg[node] = 0;
    }
    if (CLEANUP && blockIdx.x == 0) {
        if (threadIdx.x < 2 * D) g_bnsums[threadIdx.x] = 0.0f;
        if (threadIdx.x == 0) g_total = 0;
    }
}

// ---------------- BN statistics: per-feature sum & sum of squares ----------------
__global__ __launch_bounds__(512) void bnstat_kernel(const float* __restrict__ agg, int n) {
    int f = threadIdx.x & (D - 1);
    int g = threadIdx.x >> 7;
    int r0 = blockIdx.x * 512 + g;
    int rend = min(n, (int)(blockIdx.x * 512 + 512));
    float s = 0.f, s2 = 0.f;
    for (int r = r0; r < rend; r += 4) {
        float v = agg[(size_t)r * D + f];
        s += v;
        s2 = fmaf(v, v, s2);
    }
    atomicAdd(&g_bnsums[f], s);
    atomicAdd(&g_bnsums[D + f], s2);
}

extern "C" void kernel_launch(void* const* d_in, const int* in_sizes, int n_in,
                              void* d_out, int out_size)
{
    const float* x     = (const float*)d_in[0];
    const int*   ei    = (const int*)  d_in[1];
    const float* W1    = (const float*)d_in[2];
    const float* b1    = (const float*)d_in[3];
    const float* gamma = (const float*)d_in[4];
    const float* beta  = (const float*)d_in[5];
    const float* W2    = (const float*)d_in[6];
    const float* b2    = (const float*)d_in[7];
    float* out = (float*)d_out;

    int n = in_sizes[0] / D;
    int E = in_sizes[1] / 2;
    const int* src = ei;
    const int* dst = ei + E;
    float invN = 1.0f / (float)n;

    int smem = (D * D + TM * D + 2 * D) * (int)sizeof(float);  // 99328 B
    cudaFuncSetAttribute(gemm_kernel,
                         cudaFuncAttributeMaxDynamicSharedMemorySize, smem);

    void* p;
    cudaGetSymbolAddress(&p, g_h);   float* hbuf   = (float*)p;
    cudaGetSymbolAddress(&p, g_agg); float* aggbuf = (float*)p;

    int nb = (n + 255) / 256;
    int gblocks = (n + TM - 1) / TM;
    int sblocks = (n * 32 + 255) / 256;

    // prep: degrees -> bucket offsets -> bucket fill
    deg_kernel<<<(E + 255) / 256, 256>>>(dst, E);
    alloc_kernel<<<nb, 256>>>(n);
    fill_kernel<<<(E + 255) / 256, 256>>>(src, dst, E);

    // conv1
    gemm_kernel<<<gblocks, 256, smem>>>(x, W1, hbuf, n, 0, nullptr, nullptr, invN);
    scatter_csr_kernel<0><<<sblocks, 256>>>(hbuf, aggbuf, b1, n);

    // BN stats over conv1 output
    bnstat_kernel<<<(n + 511) / 512, 512>>>(aggbuf, n);

    // conv2 (BN+ReLU fused into X load; scratch cleanup fused into scatter2)
    gemm_kernel<<<gblocks, 256, smem>>>(aggbuf, W2, hbuf, n, 1, gamma, beta, invN);
    scatter_csr_kernel<1><<<sblocks, 256>>>(hbuf, out, b2, n);
}

// round 7
// speedup vs baseline: 1.6673x; 1.2996x over previous
#include <cuda_runtime.h>
#include <cuda_bf16.h>
#include <cstdint>

#define D    128
#define MAXN 50048
#define MAXE 1000000
#define PITCH 136          // bf16 elements per smem row (conflict-free fragment LDS)

// ---- scratch (zero-initialized at module load; re-zeroed by scatter2 epilogue) ----
__device__ float g_dinv[MAXN];
__device__ int   g_deg[MAXN];       // must be 0 at start of every replay
__device__ int   g_rowptr[MAXN];
__device__ int   g_cursor[MAXN];
__device__ int   g_csr[MAXE];
__device__ float g_h[(size_t)MAXN * D];
__device__ float g_agg[(size_t)MAXN * D];
__device__ float g_bnsums[2 * D];   // must be 0 at start of every replay
__device__ int   g_total;           // must be 0 at start of every replay
// bf16 hi/lo images of W^T, plain [n][k] row-major
__device__ __nv_bfloat16 g_w1hi[D * D], g_w1lo[D * D];
__device__ __nv_bfloat16 g_w2hi[D * D], g_w2lo[D * D];

__device__ __forceinline__ uint32_t packbf(__nv_bfloat16 a, __nv_bfloat16 b) {
    return (uint32_t)__bfloat16_as_ushort(a) | ((uint32_t)__bfloat16_as_ushort(b) << 16);
}

// warp mma: D(m16n8,f32) += A(m16k16,bf16) * B(k16n8,bf16)
__device__ __forceinline__ void mma16816(float* c, uint32_t a0, uint32_t a1,
                                         uint32_t a2, uint32_t a3,
                                         uint32_t b0, uint32_t b1) {
    asm volatile(
        "mma.sync.aligned.m16n8k16.row.col.f32.bf16.bf16.f32 "
        "{%0,%1,%2,%3}, {%4,%5,%6,%7}, {%8,%9}, {%0,%1,%2,%3};"
        : "+f"(c[0]), "+f"(c[1]), "+f"(c[2]), "+f"(c[3])
        : "r"(a0), "r"(a1), "r"(a2), "r"(a3), "r"(b0), "r"(b1));
}

// ---------------- W image prep: Wt[n][k] bf16 hi/lo ----------------
__global__ void wprep_kernel(const float* __restrict__ W1, const float* __restrict__ W2) {
    int idx = blockIdx.x * blockDim.x + threadIdx.x;   // 0 .. 2*16384-1
    int which = idx >> 14;
    int e = idx & 16383;
    const float* W = which ? W2 : W1;
    float v = W[e];
    int k = e >> 7, nn = e & 127;                      // W[k][nn]
    __nv_bfloat16 hi = __float2bfloat16(v);
    __nv_bfloat16 lo = __float2bfloat16(v - __bfloat162float(hi));
    int off = nn * D + k;                              // Wt[n][k]
    if (which) { g_w2hi[off] = hi; g_w2lo[off] = lo; }
    else       { g_w1hi[off] = hi; g_w1lo[off] = lo; }
}

// ---------------- degree histogram over edge destinations ----------------
__global__ void deg_kernel(const int* __restrict__ dst, int E) {
    int e = blockIdx.x * blockDim.x + threadIdx.x;
    if (e < E) atomicAdd(&g_deg[dst[e]], 1);
}

// ---------------- bucket allocation (order-free CSR offsets) + dinv ----------------
__global__ void alloc_kernel(int n) {
    int i = blockIdx.x * blockDim.x + threadIdx.x;
    if (i < n) {
        int dg = g_deg[i];
        int rp = atomicAdd(&g_total, dg);
        g_rowptr[i] = rp;
        g_cursor[i] = rp;
        g_dinv[i] = rsqrtf(1.0f + (float)dg);
    }
}

// ---------------- bucket fill: csr[dst buckets] = src ----------------
__global__ void fill_kernel(const int* __restrict__ src, const int* __restrict__ dst, int E) {
    int e = blockIdx.x * blockDim.x + threadIdx.x;
    if (e < E) {
        int pos = atomicAdd(&g_cursor[dst[e]], 1);
        g_csr[pos] = src[e];
    }
}

// ---------------- HMMA GEMM: Hout = (X @ W) * dinv[row]  (BN+ReLU on X if asked)
// bf16x3 emulated fp32: Ahi*Bhi + Ahi*Blo + Alo*Bhi.
// CTA = 64 rows; 8 warps = 4 row-tiles(m16) x 2 col-halves(n64).
__global__ __launch_bounds__(256, 2) void gemm_mma_kernel(
    const float* __restrict__ X,
    const __nv_bfloat16* __restrict__ Wthi, const __nv_bfloat16* __restrict__ Wtlo,
    float* __restrict__ Hout, int n, int use_bn,
    const float* __restrict__ gamma, const float* __restrict__ beta, float invN)
{
    extern __shared__ __align__(16) char sm[];
    __nv_bfloat16* sWhi = (__nv_bfloat16*)sm;                       // 128 x PITCH
    __nv_bfloat16* sWlo = sWhi + D * PITCH;
    __nv_bfloat16* sXhi = sWlo + D * PITCH;                         // 64 x PITCH
    __nv_bfloat16* sXlo = sXhi + 64 * PITCH;
    __shared__ float scale_s[D], shift_s[D];

    int tid  = threadIdx.x;
    int wid  = tid >> 5;
    int lane = tid & 31;

    if (use_bn && tid < D) {
        float mu  = g_bnsums[tid] * invN;
        float var = g_bnsums[D + tid] * invN - mu * mu;
        float sc  = gamma[tid] * rsqrtf(var + 1e-5f);
        scale_s[tid] = sc;
        shift_s[tid] = beta[tid] - mu * sc;
    }

    // stage W hi/lo: 2048 uint4 each; dst row pitch = 272 B (17 uint4)
    {
        const uint4* wh = (const uint4*)Wthi;
        const uint4* wl = (const uint4*)Wtlo;
#pragma unroll
        for (int i = 0; i < 8; i++) {
            int j = tid + i * 256;            // 0..2047
            int row = j >> 4, chunk = j & 15;
            *(uint4*)((char*)sWhi + row * (PITCH * 2) + chunk * 16) = wh[j];
            *(uint4*)((char*)sWlo + row * (PITCH * 2) + chunk * 16) = wl[j];
        }
    }
    if (use_bn) __syncthreads();   // scale_s ready before X staging uses it

    // stage X hi/lo (64 rows), BN+ReLU fused
    int row0 = blockIdx.x * 64;
#pragma unroll
    for (int i = 0; i < 8; i++) {
        int idx = tid + i * 256;              // 0..2047
        int r = idx >> 5, c4 = idx & 31, k0 = c4 * 4;
        int grow = row0 + r;
        float4 v = make_float4(0.f, 0.f, 0.f, 0.f);
        if (grow < n) v = ((const float4*)X)[(size_t)grow * 32 + c4];
        if (use_bn) {
            v.x = fmaxf(0.f, fmaf(v.x, scale_s[k0 + 0], shift_s[k0 + 0]));
            v.y = fmaxf(0.f, fmaf(v.y, scale_s[k0 + 1], shift_s[k0 + 1]));
            v.z = fmaxf(0.f, fmaf(v.z, scale_s[k0 + 2], shift_s[k0 + 2]));
            v.w = fmaxf(0.f, fmaf(v.w, scale_s[k0 + 3], shift_s[k0 + 3]));
        }
        __nv_bfloat16 hx = __float2bfloat16(v.x), hy = __float2bfloat16(v.y);
        __nv_bfloat16 hz = __float2bfloat16(v.z), hw = __float2bfloat16(v.w);
        __nv_bfloat16 lx = __float2bfloat16(v.x - __bfloat162float(hx));
        __nv_bfloat16 ly = __float2bfloat16(v.y - __bfloat162float(hy));
        __nv_bfloat16 lz = __float2bfloat16(v.z - __bfloat162float(hz));
        __nv_bfloat16 lw = __float2bfloat16(v.w - __bfloat162float(hw));
        int off = r * PITCH + k0;
        *(uint2*)(sXhi + off) = make_uint2(packbf(hx, hy), packbf(hz, hw));
        *(uint2*)(sXlo + off) = make_uint2(packbf(lx, ly), packbf(lz, lw));
    }
    __syncthreads();

    int wr = wid & 3;        // row tile (m16)
    int wc = wid >> 2;       // col half (n64)
    int qrow = lane >> 2;    // 0..7
    int qk   = (lane & 3) * 2;

    float acc[8][4];
#pragma unroll
    for (int t = 0; t < 8; t++)
#pragma unroll
        for (int c = 0; c < 4; c++) acc[t][c] = 0.f;

    const __nv_bfloat16* aHbase = sXhi + (wr * 16 + qrow) * PITCH + qk;
    const __nv_bfloat16* aLbase = sXlo + (wr * 16 + qrow) * PITCH + qk;
    const __nv_bfloat16* bHbase = sWhi + (wc * 64 + qrow) * PITCH + qk;
    const __nv_bfloat16* bLbase = sWlo + (wc * 64 + qrow) * PITCH + qk;

#pragma unroll
    for (int ks = 0; ks < 8; ks++) {
        int ko = ks * 16;
        uint32_t ah0 = *(const uint32_t*)(aHbase + ko);
        uint32_t ah1 = *(const uint32_t*)(aHbase + ko + 8 * PITCH);
        uint32_t ah2 = *(const uint32_t*)(aHbase + ko + 8);
        uint32_t ah3 = *(const uint32_t*)(aHbase + ko + 8 * PITCH + 8);
        uint32_t al0 = *(const uint32_t*)(aLbase + ko);
        uint32_t al1 = *(const uint32_t*)(aLbase + ko + 8 * PITCH);
        uint32_t al2 = *(const uint32_t*)(aLbase + ko + 8);
        uint32_t al3 = *(const uint32_t*)(aLbase + ko + 8 * PITCH + 8);
#pragma unroll
        for (int nt = 0; nt < 8; nt++) {
            const __nv_bfloat16* bh = bHbase + nt * 8 * PITCH + ko;
            const __nv_bfloat16* bl = bLbase + nt * 8 * PITCH + ko;
            uint32_t bh0 = *(const uint32_t*)bh;
            uint32_t bh1 = *(const uint32_t*)(bh + 8);
            uint32_t bl0 = *(const uint32_t*)bl;
            uint32_t bl1 = *(const uint32_t*)(bl + 8);
            mma16816(acc[nt], ah0, ah1, ah2, ah3, bh0, bh1);
            mma16816(acc[nt], ah0, ah1, ah2, ah3, bl0, bl1);
            mma16816(acc[nt], al0, al1, al2, al3, bh0, bh1);
        }
    }

    // epilogue: scale by dinv[row], direct float2 stores
    {
        int r0 = row0 + wr * 16 + qrow;
        int r1 = r0 + 8;
        float dv0 = (r0 < n) ? g_dinv[r0] : 0.f;
        float dv1 = (r1 < n) ? g_dinv[r1] : 0.f;
        int colbase = wc * 64 + qk;
#pragma unroll
        for (int nt = 0; nt < 8; nt++) {
            int col = colbase + nt * 8;
            if (r0 < n)
                *(float2*)(Hout + (size_t)r0 * D + col) =
                    make_float2(acc[nt][0] * dv0, acc[nt][1] * dv0);
            if (r1 < n)
                *(float2*)(Hout + (size_t)r1 * D + col) =
                    make_float2(acc[nt][2] * dv1, acc[nt][3] * dv1);
        }
    }
}

// ---------------- CSR scatter: out[d] = (hs[d] + sum_{s in N(d)} hs[s]) * dinv[d] + bias
template <int CLEANUP>
__global__ __launch_bounds__(256) void scatter_csr_kernel(
    const float* __restrict__ hs, float* __restrict__ out,
    const float* __restrict__ bias, int n)
{
    int node = (blockIdx.x * blockDim.x + threadIdx.x) >> 5;
    int lane = threadIdx.x & 31;
    if (node < n) {
        size_t base = (size_t)node * D + lane * 4;
        float4 acc = *(const float4*)(hs + base);   // self loop
        int start = g_rowptr[node];
        int cnt   = g_deg[node];
        int j = 0;
        for (; j + 4 <= cnt; j += 4) {
            int s0 = __ldg(&g_csr[start + j + 0]);
            int s1 = __ldg(&g_csr[start + j + 1]);
            int s2 = __ldg(&g_csr[start + j + 2]);
            int s3 = __ldg(&g_csr[start + j + 3]);
            float4 v0 = *(const float4*)(hs + (size_t)s0 * D + lane * 4);
            float4 v1 = *(const float4*)(hs + (size_t)s1 * D + lane * 4);
            float4 v2 = *(const float4*)(hs + (size_t)s2 * D + lane * 4);
            float4 v3 = *(const float4*)(hs + (size_t)s3 * D + lane * 4);
            acc.x += (v0.x + v1.x) + (v2.x + v3.x);
            acc.y += (v0.y + v1.y) + (v2.y + v3.y);
            acc.z += (v0.z + v1.z) + (v2.z + v3.z);
            acc.w += (v0.w + v1.w) + (v2.w + v3.w);
        }
        for (; j < cnt; j++) {
            int s = __ldg(&g_csr[start + j]);
            float4 v = *(const float4*)(hs + (size_t)s * D + lane * 4);
            acc.x += v.x; acc.y += v.y; acc.z += v.z; acc.w += v.w;
        }
        float dv = g_dinv[node];
        float4 bv = ((const float4*)bias)[lane];
        float4 o;
        o.x = fmaf(acc.x, dv, bv.x);
        o.y = fmaf(acc.y, dv, bv.y);
        o.z = fmaf(acc.z, dv, bv.z);
        o.w = fmaf(acc.w, dv, bv.w);
        *(float4*)(out + base) = o;

        if (CLEANUP && lane == 0) g_deg[node] = 0;
    }
    if (CLEANUP && blockIdx.x == 0) {
        if (threadIdx.x < 2 * D) g_bnsums[threadIdx.x] = 0.0f;
        if (threadIdx.x == 0) g_total = 0;
    }
}

// ---------------- BN statistics: per-feature sum & sum of squares ----------------
__global__ __launch_bounds__(512) void bnstat_kernel(const float* __restrict__ agg, int n) {
    int f = threadIdx.x & (D - 1);
    int g = threadIdx.x >> 7;
    int r0 = blockIdx.x * 512 + g;
    int rend = min(n, (int)(blockIdx.x * 512 + 512));
    float s = 0.f, s2 = 0.f;
    for (int r = r0; r < rend; r += 4) {
        float v = agg[(size_t)r * D + f];
        s += v;
        s2 = fmaf(v, v, s2);
    }
    atomicAdd(&g_bnsums[f], s);
    atomicAdd(&g_bnsums[D + f], s2);
}

extern "C" void kernel_launch(void* const* d_in, const int* in_sizes, int n_in,
                              void* d_out, int out_size)
{
    const float* x     = (const float*)d_in[0];
    const int*   ei    = (const int*)  d_in[1];
    const float* W1    = (const float*)d_in[2];
    const float* b1    = (const float*)d_in[3];
    const float* gamma = (const float*)d_in[4];
    const float* beta  = (const float*)d_in[5];
    const float* W2    = (const float*)d_in[6];
    const float* b2    = (const float*)d_in[7];
    float* out = (float*)d_out;

    int n = in_sizes[0] / D;
    int E = in_sizes[1] / 2;
    const int* src = ei;
    const int* dst = ei + E;
    float invN = 1.0f / (float)n;

    // dyn smem: W hi/lo (128*PITCH each) + X hi/lo (64*PITCH each), bf16
    int smem_mma = (2 * D * PITCH + 2 * 64 * PITCH) * 2;   // 104448 B
    cudaFuncSetAttribute(gemm_mma_kernel,
                         cudaFuncAttributeMaxDynamicSharedMemorySize, smem_mma);

    void* p;
    cudaGetSymbolAddress(&p, g_h);    float* hbuf   = (float*)p;
    cudaGetSymbolAddress(&p, g_agg);  float* aggbuf = (float*)p;
    cudaGetSymbolAddress(&p, g_w1hi); const __nv_bfloat16* w1hi = (const __nv_bfloat16*)p;
    cudaGetSymbolAddress(&p, g_w1lo); const __nv_bfloat16* w1lo = (const __nv_bfloat16*)p;
    cudaGetSymbolAddress(&p, g_w2hi); const __nv_bfloat16* w2hi = (const __nv_bfloat16*)p;
    cudaGetSymbolAddress(&p, g_w2lo); const __nv_bfloat16* w2lo = (const __nv_bfloat16*)p;

    int nb = (n + 255) / 256;
    int gblocks = (n + 63) / 64;
    int sblocks = (n * 32 + 255) / 256;

    // prep: W images + degrees -> bucket offsets -> bucket fill
    wprep_kernel<<<(2 * D * D) / 256, 256>>>(W1, W2);
    deg_kernel<<<(E + 255) / 256, 256>>>(dst, E);
    alloc_kernel<<<nb, 256>>>(n);
    fill_kernel<<<(E + 255) / 256, 256>>>(src, dst, E);

    // conv1
    gemm_mma_kernel<<<gblocks, 256, smem_mma>>>(x, w1hi, w1lo, hbuf, n, 0,
                                                nullptr, nullptr, invN);
    scatter_csr_kernel<0><<<sblocks, 256>>>(hbuf, aggbuf, b1, n);

    // BN stats over conv1 output
    bnstat_kernel<<<(n + 511) / 512, 512>>>(aggbuf, n);

    // conv2 (BN+ReLU fused into X staging; scratch cleanup fused into scatter2)
    gemm_mma_kernel<<<gblocks, 256, smem_mma>>>(aggbuf, w2hi, w2lo, hbuf, n, 1,
                                                gamma, beta, invN);
    scatter_csr_kernel<1><<<sblocks, 256>>>(hbuf, out, b2, n);
}

// round 8
// speedup vs baseline: 1.7134x; 1.0276x over previous
#include <cuda_runtime.h>
#include <cuda_bf16.h>
#include <cstdint>

#define D    128
#define MAXN 50048
#define MAXE 1000000
#define PITCH 136          // bf16 elements per smem row (conflict-free fragment LDS)

// ---- scratch (zero-initialized at module load; re-zeroed by scatter2 epilogue) ----
__device__ float g_dinv[MAXN];
__device__ int   g_deg[MAXN];       // must be 0 at start of every replay
__device__ int   g_rowptr[MAXN];
__device__ int   g_cursor[MAXN];
__device__ int   g_csr[MAXE];
__device__ float g_h[(size_t)MAXN * D];
__device__ float g_agg[(size_t)MAXN * D];
__device__ float g_bnsums[2 * D];   // must be 0 at start of every replay
__device__ int   g_total;           // must be 0 at start of every replay
// bf16 hi/lo images of W^T, plain [n][k] row-major
__device__ __nv_bfloat16 g_w1hi[D * D], g_w1lo[D * D];
__device__ __nv_bfloat16 g_w2hi[D * D], g_w2lo[D * D];

__device__ __forceinline__ uint32_t packbf(__nv_bfloat16 a, __nv_bfloat16 b) {
    return (uint32_t)__bfloat16_as_ushort(a) | ((uint32_t)__bfloat16_as_ushort(b) << 16);
}

// warp mma: D(m16n8,f32) += A(m16k16,bf16) * B(k16n8,bf16)
__device__ __forceinline__ void mma16816(float* c, const uint32_t* a,
                                         uint32_t b0, uint32_t b1) {
    asm volatile(
        "mma.sync.aligned.m16n8k16.row.col.f32.bf16.bf16.f32 "
        "{%0,%1,%2,%3}, {%4,%5,%6,%7}, {%8,%9}, {%0,%1,%2,%3};"
        : "+f"(c[0]), "+f"(c[1]), "+f"(c[2]), "+f"(c[3])
        : "r"(a[0]), "r"(a[1]), "r"(a[2]), "r"(a[3]), "r"(b0), "r"(b1));
}
#define LDSM_X4(r, addr)                                                     \
    asm volatile("ldmatrix.sync.aligned.m8n8.x4.shared.b16 {%0,%1,%2,%3}, [%4];" \
        : "=r"((r)[0]), "=r"((r)[1]), "=r"((r)[2]), "=r"((r)[3]) : "r"(addr))

// ---------------- fused prep: W images (bf16 hi/lo, Wt[n][k]) + degree histogram
__global__ void prep_kernel(const int* __restrict__ dst, int E,
                            const float* __restrict__ W1, const float* __restrict__ W2) {
    int i = blockIdx.x * blockDim.x + threadIdx.x;
    if (i < 2 * D * D) {
        int which = i >> 14;
        int e = i & 16383;
        float v = (which ? W2 : W1)[e];
        int k = e >> 7, nn = e & 127;                  // W[k][nn]
        __nv_bfloat16 hi = __float2bfloat16(v);
        __nv_bfloat16 lo = __float2bfloat16(v - __bfloat162float(hi));
        int off = nn * D + k;                          // Wt[n][k]
        if (which) { g_w2hi[off] = hi; g_w2lo[off] = lo; }
        else       { g_w1hi[off] = hi; g_w1lo[off] = lo; }
    }
    int base = i * 4;
    if (base + 3 < E) {
        int4 d = *(const int4*)(dst + base);
        atomicAdd(&g_deg[d.x], 1);
        atomicAdd(&g_deg[d.y], 1);
        atomicAdd(&g_deg[d.z], 1);
        atomicAdd(&g_deg[d.w], 1);
    } else {
        for (int u = base; u < E; u++) atomicAdd(&g_deg[dst[u]], 1);
    }
}

// ---------------- bucket allocation (order-free CSR offsets) + dinv ----------------
__global__ void alloc_kernel(int n) {
    int i = blockIdx.x * blockDim.x + threadIdx.x;
    if (i < n) {
        int dg = g_deg[i];
        int rp = atomicAdd(&g_total, dg);
        g_rowptr[i] = rp;
        g_cursor[i] = rp;
        g_dinv[i] = rsqrtf(1.0f + (float)dg);
    }
}

// ---------------- bucket fill: csr[dst buckets] = src (4 edges per thread) ----------------
__global__ void fill_kernel(const int* __restrict__ src, const int* __restrict__ dst, int E) {
    int i = blockIdx.x * blockDim.x + threadIdx.x;
    int base = i * 4;
    if (base + 3 < E) {
        int4 d = *(const int4*)(dst + base);
        int4 s = *(const int4*)(src + base);
        g_csr[atomicAdd(&g_cursor[d.x], 1)] = s.x;
        g_csr[atomicAdd(&g_cursor[d.y], 1)] = s.y;
        g_csr[atomicAdd(&g_cursor[d.z], 1)] = s.z;
        g_csr[atomicAdd(&g_cursor[d.w], 1)] = s.w;
    } else {
        for (int u = base; u < E; u++)
            g_csr[atomicAdd(&g_cursor[dst[u]], 1)] = src[u];
    }
}

// ---------------- HMMA GEMM: Hout = (X @ W) * dinv[row]  (BN+ReLU on X if asked)
// bf16x3 emulated fp32: Ahi*Bhi + Ahi*Blo + Alo*Bhi. ldmatrix fragment loads.
// CTA = 64 rows; 8 warps = 4 row-tiles(m16) x 2 col-halves(n64).
__global__ __launch_bounds__(256, 2) void gemm_mma_kernel(
    const float* __restrict__ X,
    const __nv_bfloat16* __restrict__ Wthi, const __nv_bfloat16* __restrict__ Wtlo,
    float* __restrict__ Hout, int n, int use_bn,
    const float* __restrict__ gamma, const float* __restrict__ beta, float invN)
{
    extern __shared__ __align__(16) char sm[];
    __nv_bfloat16* sWhi = (__nv_bfloat16*)sm;                       // 128 x PITCH
    __nv_bfloat16* sWlo = sWhi + D * PITCH;
    __nv_bfloat16* sXhi = sWlo + D * PITCH;                         // 64 x PITCH
    __nv_bfloat16* sXlo = sXhi + 64 * PITCH;
    __shared__ float scale_s[D], shift_s[D];

    int tid  = threadIdx.x;
    int wid  = tid >> 5;
    int lane = tid & 31;

    if (use_bn && tid < D) {
        float mu  = g_bnsums[tid] * invN;
        float var = g_bnsums[D + tid] * invN - mu * mu;
        float sc  = gamma[tid] * rsqrtf(var + 1e-5f);
        scale_s[tid] = sc;
        shift_s[tid] = beta[tid] - mu * sc;
    }

    // stage W hi/lo: 2048 uint4 each; dst row pitch = 272 B (17 uint4)
    {
        const uint4* wh = (const uint4*)Wthi;
        const uint4* wl = (const uint4*)Wtlo;
#pragma unroll
        for (int i = 0; i < 8; i++) {
            int j = tid + i * 256;            // 0..2047
            int row = j >> 4, chunk = j & 15;
            *(uint4*)((char*)sWhi + row * (PITCH * 2) + chunk * 16) = wh[j];
            *(uint4*)((char*)sWlo + row * (PITCH * 2) + chunk * 16) = wl[j];
        }
    }
    if (use_bn) __syncthreads();   // scale_s ready before X staging uses it

    // stage X hi/lo (64 rows), BN+ReLU fused
    int row0 = blockIdx.x * 64;
#pragma unroll
    for (int i = 0; i < 8; i++) {
        int idx = tid + i * 256;              // 0..2047
        int r = idx >> 5, c4 = idx & 31, k0 = c4 * 4;
        int grow = row0 + r;
        float4 v = make_float4(0.f, 0.f, 0.f, 0.f);
        if (grow < n) v = ((const float4*)X)[(size_t)grow * 32 + c4];
        if (use_bn) {
            v.x = fmaxf(0.f, fmaf(v.x, scale_s[k0 + 0], shift_s[k0 + 0]));
            v.y = fmaxf(0.f, fmaf(v.y, scale_s[k0 + 1], shift_s[k0 + 1]));
            v.z = fmaxf(0.f, fmaf(v.z, scale_s[k0 + 2], shift_s[k0 + 2]));
            v.w = fmaxf(0.f, fmaf(v.w, scale_s[k0 + 3], shift_s[k0 + 3]));
        }
        __nv_bfloat16 hx = __float2bfloat16(v.x), hy = __float2bfloat16(v.y);
        __nv_bfloat16 hz = __float2bfloat16(v.z), hw = __float2bfloat16(v.w);
        __nv_bfloat16 lx = __float2bfloat16(v.x - __bfloat162float(hx));
        __nv_bfloat16 ly = __float2bfloat16(v.y - __bfloat162float(hy));
        __nv_bfloat16 lz = __float2bfloat16(v.z - __bfloat162float(hz));
        __nv_bfloat16 lw = __float2bfloat16(v.w - __bfloat162float(hw));
        int off = r * PITCH + k0;
        *(uint2*)(sXhi + off) = make_uint2(packbf(hx, hy), packbf(hz, hw));
        *(uint2*)(sXlo + off) = make_uint2(packbf(lx, ly), packbf(lz, lw));
    }
    __syncthreads();

    int wr = wid & 3;        // row tile (m16)
    int wc = wid >> 2;       // col half (n64)

    float acc[8][4];
#pragma unroll
    for (int t = 0; t < 8; t++)
#pragma unroll
        for (int c = 0; c < 4; c++) acc[t][c] = 0.f;

    // ldmatrix lane-address bases (byte offsets in shared space)
    // A x4: lanes 0-15 -> rows (wr*16 + lane&15), col 0; lanes 16-31 -> same rows, col 8
    uint32_t aRow = (uint32_t)(wr * 16 + (lane & 15));
    uint32_t aCol = (uint32_t)((lane >> 4) << 3);
    uint32_t aOff = (aRow * PITCH + aCol) * 2;
    uint32_t aHb = (uint32_t)__cvta_generic_to_shared(sXhi) + aOff;
    uint32_t aLb = (uint32_t)__cvta_generic_to_shared(sXlo) + aOff;
    // B x4 (two n8-tiles per load): lane groups -> (n row, k col) per matrix order
    uint32_t bRowL = (uint32_t)((lane & 7) + ((lane & 16) >> 1));   // +8 for lanes>=16
    uint32_t bColL = (uint32_t)(lane & 8);
    uint32_t bHb[4], bLb[4];
#pragma unroll
    for (int ntp = 0; ntp < 4; ntp++) {
        uint32_t row = (uint32_t)(wc * 64 + ntp * 16) + bRowL;
        uint32_t off = (row * PITCH + bColL) * 2;
        bHb[ntp] = (uint32_t)__cvta_generic_to_shared(sWhi) + off;
        bLb[ntp] = (uint32_t)__cvta_generic_to_shared(sWlo) + off;
    }

#pragma unroll
    for (int ks = 0; ks < 8; ks++) {
        uint32_t ko2 = (uint32_t)(ks * 32);   // 16 bf16 cols = 32 bytes
        uint32_t ah[4], al[4];
        LDSM_X4(ah, aHb + ko2);
        LDSM_X4(al, aLb + ko2);
#pragma unroll
        for (int ntp = 0; ntp < 4; ntp++) {
            uint32_t bh[4], bl[4];
            LDSM_X4(bh, bHb[ntp] + ko2);   // {b0,b1} of nt=2ntp, {b0,b1} of nt=2ntp+1
            LDSM_X4(bl, bLb[ntp] + ko2);
            mma16816(acc[2 * ntp + 0], ah, bh[0], bh[1]);
            mma16816(acc[2 * ntp + 0], ah, bl[0], bl[1]);
            mma16816(acc[2 * ntp + 0], al, bh[0], bh[1]);
            mma16816(acc[2 * ntp + 1], ah, bh[2], bh[3]);
            mma16816(acc[2 * ntp + 1], ah, bl[2], bl[3]);
            mma16816(acc[2 * ntp + 1], al, bh[2], bh[3]);
        }
    }

    // epilogue: scale by dinv[row], direct float2 stores
    {
        int qrow = lane >> 2;
        int qk   = (lane & 3) * 2;
        int r0 = row0 + wr * 16 + qrow;
        int r1 = r0 + 8;
        float dv0 = (r0 < n) ? g_dinv[r0] : 0.f;
        float dv1 = (r1 < n) ? g_dinv[r1] : 0.f;
        int colbase = wc * 64 + qk;
#pragma unroll
        for (int nt = 0; nt < 8; nt++) {
            int col = colbase + nt * 8;
            if (r0 < n)
                *(float2*)(Hout + (size_t)r0 * D + col) =
                    make_float2(acc[nt][0] * dv0, acc[nt][1] * dv0);
            if (r1 < n)
                *(float2*)(Hout + (size_t)r1 * D + col) =
                    make_float2(acc[nt][2] * dv1, acc[nt][3] * dv1);
        }
    }
}

// ---------------- CSR scatter: out[d] = (hs[d] + sum_{s in N(d)} hs[s]) * dinv[d] + bias
template <int CLEANUP>
__global__ __launch_bounds__(256) void scatter_csr_kernel(
    const float* __restrict__ hs, float* __restrict__ out,
    const float* __restrict__ bias, int n)
{
    int node = (blockIdx.x * blockDim.x + threadIdx.x) >> 5;
    int lane = threadIdx.x & 31;
    if (node < n) {
        size_t base = (size_t)node * D + lane * 4;
        float4 acc = *(const float4*)(hs + base);   // self loop
        int start = g_rowptr[node];
        int cnt   = g_deg[node];
        int j = 0;
        for (; j + 4 <= cnt; j += 4) {
            int s0 = __ldg(&g_csr[start + j + 0]);
            int s1 = __ldg(&g_csr[start + j + 1]);
            int s2 = __ldg(&g_csr[start + j + 2]);
            int s3 = __ldg(&g_csr[start + j + 3]);
            float4 v0 = *(const float4*)(hs + (size_t)s0 * D + lane * 4);
            float4 v1 = *(const float4*)(hs + (size_t)s1 * D + lane * 4);
            float4 v2 = *(const float4*)(hs + (size_t)s2 * D + lane * 4);
            float4 v3 = *(const float4*)(hs + (size_t)s3 * D + lane * 4);
            acc.x += (v0.x + v1.x) + (v2.x + v3.x);
            acc.y += (v0.y + v1.y) + (v2.y + v3.y);
            acc.z += (v0.z + v1.z) + (v2.z + v3.z);
            acc.w += (v0.w + v1.w) + (v2.w + v3.w);
        }
        for (; j < cnt; j++) {
            int s = __ldg(&g_csr[start + j]);
            float4 v = *(const float4*)(hs + (size_t)s * D + lane * 4);
            acc.x += v.x; acc.y += v.y; acc.z += v.z; acc.w += v.w;
        }
        float dv = g_dinv[node];
        float4 bv = ((const float4*)bias)[lane];
        float4 o;
        o.x = fmaf(acc.x, dv, bv.x);
        o.y = fmaf(acc.y, dv, bv.y);
        o.z = fmaf(acc.z, dv, bv.z);
        o.w = fmaf(acc.w, dv, bv.w);
        *(float4*)(out + base) = o;

        if (CLEANUP && lane == 0) g_deg[node] = 0;
    }
    if (CLEANUP && blockIdx.x == 0) {
        if (threadIdx.x < 2 * D) g_bnsums[threadIdx.x] = 0.0f;
        if (threadIdx.x == 0) g_total = 0;
    }
}

// ---------------- BN statistics: per-feature sum & sum of squares ----------------
__global__ __launch_bounds__(512) void bnstat_kernel(const float* __restrict__ agg, int n) {
    int f = threadIdx.x & (D - 1);
    int g = threadIdx.x >> 7;
    int r0 = blockIdx.x * 512 + g;
    int rend = min(n, (int)(blockIdx.x * 512 + 512));
    float s = 0.f, s2 = 0.f;
    for (int r = r0; r < rend; r += 4) {
        float v = agg[(size_t)r * D + f];
        s += v;
        s2 = fmaf(v, v, s2);
    }
    atomicAdd(&g_bnsums[f], s);
    atomicAdd(&g_bnsums[D + f], s2);
}

extern "C" void kernel_launch(void* const* d_in, const int* in_sizes, int n_in,
                              void* d_out, int out_size)
{
    const float* x     = (const float*)d_in[0];
    const int*   ei    = (const int*)  d_in[1];
    const float* W1    = (const float*)d_in[2];
    const float* b1    = (const float*)d_in[3];
    const float* gamma = (const float*)d_in[4];
    const float* beta  = (const float*)d_in[5];
    const float* W2    = (const float*)d_in[6];
    const float* b2    = (const float*)d_in[7];
    float* out = (float*)d_out;

    int n = in_sizes[0] / D;
    int E = in_sizes[1] / 2;
    const int* src = ei;
    const int* dst = ei + E;
    float invN = 1.0f / (float)n;

    // dyn smem: W hi/lo (128*PITCH each) + X hi/lo (64*PITCH each), bf16
    int smem_mma = (2 * D * PITCH + 2 * 64 * PITCH) * 2;   // 104448 B
    cudaFuncSetAttribute(gemm_mma_kernel,
                         cudaFuncAttributeMaxDynamicSharedMemorySize, smem_mma);

    void* p;
    cudaGetSymbolAddress(&p, g_h);    float* hbuf   = (float*)p;
    cudaGetSymbolAddress(&p, g_agg);  float* aggbuf = (float*)p;
    cudaGetSymbolAddress(&p, g_w1hi); const __nv_bfloat16* w1hi = (const __nv_bfloat16*)p;
    cudaGetSymbolAddress(&p, g_w1lo); const __nv_bfloat16* w1lo = (const __nv_bfloat16*)p;
    cudaGetSymbolAddress(&p, g_w2hi); const __nv_bfloat16* w2hi = (const __nv_bfloat16*)p;
    cudaGetSymbolAddress(&p, g_w2lo); const __nv_bfloat16* w2lo = (const __nv_bfloat16*)p;

    int nb = (n + 255) / 256;
    int gblocks = (n + 63) / 64;
    int sblocks = (n * 32 + 255) / 256;
    int e4 = (E + 3) / 4;
    int pthreads = (e4 > 2 * D * D) ? e4 : 2 * D * D;

    // prep: fused W images + degree histogram, then offsets, then bucket fill
    prep_kernel<<<(pthreads + 255) / 256, 256>>>(dst, E, W1, W2);
    alloc_kernel<<<nb, 256>>>(n);
    fill_kernel<<<(e4 + 255) / 256, 256>>>(src, dst, E);

    // conv1
    gemm_mma_kernel<<<gblocks, 256, smem_mma>>>(x, w1hi, w1lo, hbuf, n, 0,
                                                nullptr, nullptr, invN);
    scatter_csr_kernel<0><<<sblocks, 256>>>(hbuf, aggbuf, b1, n);

    // BN stats over conv1 output
    bnstat_kernel<<<(n + 511) / 512, 512>>>(aggbuf, n);

    // conv2 (BN+ReLU fused into X staging; scratch cleanup fused into scatter2)
    gemm_mma_kernel<<<gblocks, 256, smem_mma>>>(aggbuf, w2hi, w2lo, hbuf, n, 1,
                                                gamma, beta, invN);
    scatter_csr_kernel<1><<<sblocks, 256>>>(hbuf, out, b2, n);
}

// round 9
// speedup vs baseline: 1.7396x; 1.0153x over previous
#include <cuda_runtime.h>
#include <cuda_bf16.h>
#include <cstdint>

#define D    128
#define MAXN 50048
#define MAXE 1000000
#define PITCH 136          // bf16 elements per smem row (conflict-free fragment LDS)

// ---- scratch (zero-initialized at module load; re-zeroed by scatter2 epilogue) ----
__device__ float g_dinv[MAXN];
__device__ int   g_deg[MAXN];       // must be 0 at start of every replay
__device__ int   g_rowptr[MAXN];
__device__ int   g_cursor[MAXN];
__device__ int   g_csr[MAXE];
__device__ float g_h[(size_t)MAXN * D];
__device__ float g_agg[(size_t)MAXN * D];
__device__ float g_bnsums[2 * D];   // must be 0 at start of every replay
__device__ int   g_total;           // must be 0 at start of every replay
// bf16 hi/lo images of W^T, plain [n][k] row-major
__device__ __nv_bfloat16 g_w1hi[D * D], g_w1lo[D * D];
__device__ __nv_bfloat16 g_w2hi[D * D], g_w2lo[D * D];

__device__ __forceinline__ uint32_t packbf(__nv_bfloat16 a, __nv_bfloat16 b) {
    return (uint32_t)__bfloat16_as_ushort(a) | ((uint32_t)__bfloat16_as_ushort(b) << 16);
}

// warp mma: D(m16n8,f32) += A(m16k16,bf16) * B(k16n8,bf16)
__device__ __forceinline__ void mma16816(float* c, const uint32_t* a,
                                         uint32_t b0, uint32_t b1) {
    asm volatile(
        "mma.sync.aligned.m16n8k16.row.col.f32.bf16.bf16.f32 "
        "{%0,%1,%2,%3}, {%4,%5,%6,%7}, {%8,%9}, {%0,%1,%2,%3};"
        : "+f"(c[0]), "+f"(c[1]), "+f"(c[2]), "+f"(c[3])
        : "r"(a[0]), "r"(a[1]), "r"(a[2]), "r"(a[3]), "r"(b0), "r"(b1));
}
#define LDSM_X4(r, addr)                                                     \
    asm volatile("ldmatrix.sync.aligned.m8n8.x4.shared.b16 {%0,%1,%2,%3}, [%4];" \
        : "=r"((r)[0]), "=r"((r)[1]), "=r"((r)[2]), "=r"((r)[3]) : "r"(addr))

// ---------------- fused prep: W images (bf16 hi/lo, Wt[n][k]) + degree histogram
__global__ void prep_kernel(const int* __restrict__ dst, int E,
                            const float* __restrict__ W1, const float* __restrict__ W2) {
    int i = blockIdx.x * blockDim.x + threadIdx.x;
    if (i < 2 * D * D) {
        int which = i >> 14;
        int e = i & 16383;
        float v = (which ? W2 : W1)[e];
        int k = e >> 7, nn = e & 127;                  // W[k][nn]
        __nv_bfloat16 hi = __float2bfloat16(v);
        __nv_bfloat16 lo = __float2bfloat16(v - __bfloat162float(hi));
        int off = nn * D + k;                          // Wt[n][k]
        if (which) { g_w2hi[off] = hi; g_w2lo[off] = lo; }
        else       { g_w1hi[off] = hi; g_w1lo[off] = lo; }
    }
    int base = i * 4;
    if (base + 3 < E) {
        int4 d = *(const int4*)(dst + base);
        atomicAdd(&g_deg[d.x], 1);
        atomicAdd(&g_deg[d.y], 1);
        atomicAdd(&g_deg[d.z], 1);
        atomicAdd(&g_deg[d.w], 1);
    } else {
        for (int u = base; u < E; u++) atomicAdd(&g_deg[dst[u]], 1);
    }
}

// ---------------- bucket allocation (order-free CSR offsets) + dinv ----------------
__global__ void alloc_kernel(int n) {
    int i = blockIdx.x * blockDim.x + threadIdx.x;
    if (i < n) {
        int dg = g_deg[i];
        int rp = atomicAdd(&g_total, dg);
        g_rowptr[i] = rp;
        g_cursor[i] = rp;
        g_dinv[i] = rsqrtf(1.0f + (float)dg);
    }
}

// ---------------- bucket fill: csr[dst buckets] = src (4 edges per thread) ----------------
__global__ void fill_kernel(const int* __restrict__ src, const int* __restrict__ dst, int E) {
    int i = blockIdx.x * blockDim.x + threadIdx.x;
    int base = i * 4;
    if (base + 3 < E) {
        int4 d = *(const int4*)(dst + base);
        int4 s = *(const int4*)(src + base);
        g_csr[atomicAdd(&g_cursor[d.x], 1)] = s.x;
        g_csr[atomicAdd(&g_cursor[d.y], 1)] = s.y;
        g_csr[atomicAdd(&g_cursor[d.z], 1)] = s.z;
        g_csr[atomicAdd(&g_cursor[d.w], 1)] = s.w;
    } else {
        for (int u = base; u < E; u++)
            g_csr[atomicAdd(&g_cursor[dst[u]], 1)] = src[u];
    }
}

// ---------------- HMMA GEMM: Hout = (X @ W) * dinv[row]  (BN+ReLU on X if asked)
// bf16x3 emulated fp32: Ahi*Bhi + Ahi*Blo + Alo*Bhi. ldmatrix fragment loads.
// PERSISTENT: each CTA stages W once, then grid-strides over 64-row X tiles.
// 8 warps = 4 row-tiles(m16) x 2 col-halves(n64) per tile.
__global__ __launch_bounds__(256, 2) void gemm_mma_kernel(
    const float* __restrict__ X,
    const __nv_bfloat16* __restrict__ Wthi, const __nv_bfloat16* __restrict__ Wtlo,
    float* __restrict__ Hout, int n, int use_bn,
    const float* __restrict__ gamma, const float* __restrict__ beta, float invN)
{
    extern __shared__ __align__(16) char sm[];
    __nv_bfloat16* sWhi = (__nv_bfloat16*)sm;                       // 128 x PITCH
    __nv_bfloat16* sWlo = sWhi + D * PITCH;
    __nv_bfloat16* sXhi = sWlo + D * PITCH;                         // 64 x PITCH
    __nv_bfloat16* sXlo = sXhi + 64 * PITCH;
    __shared__ float scale_s[D], shift_s[D];

    int tid  = threadIdx.x;
    int wid  = tid >> 5;
    int lane = tid & 31;

    if (use_bn && tid < D) {
        float mu  = g_bnsums[tid] * invN;
        float var = g_bnsums[D + tid] * invN - mu * mu;
        float sc  = gamma[tid] * rsqrtf(var + 1e-5f);
        scale_s[tid] = sc;
        shift_s[tid] = beta[tid] - mu * sc;
    }

    // stage W hi/lo ONCE: 2048 uint4 each; dst row pitch = 272 B (17 uint4)
    {
        const uint4* wh = (const uint4*)Wthi;
        const uint4* wl = (const uint4*)Wtlo;
#pragma unroll
        for (int i = 0; i < 8; i++) {
            int j = tid + i * 256;            // 0..2047
            int row = j >> 4, chunk = j & 15;
            *(uint4*)((char*)sWhi + row * (PITCH * 2) + chunk * 16) = wh[j];
            *(uint4*)((char*)sWlo + row * (PITCH * 2) + chunk * 16) = wl[j];
        }
    }

    int wr = wid & 3;        // row tile (m16)
    int wc = wid >> 2;       // col half (n64)

    // ldmatrix lane-address bases (byte offsets in shared space)
    uint32_t aRow = (uint32_t)(wr * 16 + (lane & 15));
    uint32_t aCol = (uint32_t)((lane >> 4) << 3);
    uint32_t aOff = (aRow * PITCH + aCol) * 2;
    uint32_t aHb = (uint32_t)__cvta_generic_to_shared(sXhi) + aOff;
    uint32_t aLb = (uint32_t)__cvta_generic_to_shared(sXlo) + aOff;
    uint32_t bRowL = (uint32_t)((lane & 7) + ((lane & 16) >> 1));
    uint32_t bColL = (uint32_t)(lane & 8);
    uint32_t bHb[4], bLb[4];
#pragma unroll
    for (int ntp = 0; ntp < 4; ntp++) {
        uint32_t row = (uint32_t)(wc * 64 + ntp * 16) + bRowL;
        uint32_t off = (row * PITCH + bColL) * 2;
        bHb[ntp] = (uint32_t)__cvta_generic_to_shared(sWhi) + off;
        bLb[ntp] = (uint32_t)__cvta_generic_to_shared(sWlo) + off;
    }

    int ntiles = (n + 63) >> 6;
    for (int tile = blockIdx.x; tile < ntiles; tile += gridDim.x) {
        __syncthreads();   // W/scale ready (1st iter); X smem free (later iters)

        // stage X hi/lo (64 rows), BN+ReLU fused
        int row0 = tile * 64;
#pragma unroll
        for (int i = 0; i < 8; i++) {
            int idx = tid + i * 256;              // 0..2047
            int r = idx >> 5, c4 = idx & 31, k0 = c4 * 4;
            int grow = row0 + r;
            float4 v = make_float4(0.f, 0.f, 0.f, 0.f);
            if (grow < n) v = ((const float4*)X)[(size_t)grow * 32 + c4];
            if (use_bn) {
                v.x = fmaxf(0.f, fmaf(v.x, scale_s[k0 + 0], shift_s[k0 + 0]));
                v.y = fmaxf(0.f, fmaf(v.y, scale_s[k0 + 1], shift_s[k0 + 1]));
                v.z = fmaxf(0.f, fmaf(v.z, scale_s[k0 + 2], shift_s[k0 + 2]));
                v.w = fmaxf(0.f, fmaf(v.w, scale_s[k0 + 3], shift_s[k0 + 3]));
            }
            __nv_bfloat16 hx = __float2bfloat16(v.x), hy = __float2bfloat16(v.y);
            __nv_bfloat16 hz = __float2bfloat16(v.z), hw = __float2bfloat16(v.w);
            __nv_bfloat16 lx = __float2bfloat16(v.x - __bfloat162float(hx));
            __nv_bfloat16 ly = __float2bfloat16(v.y - __bfloat162float(hy));
            __nv_bfloat16 lz = __float2bfloat16(v.z - __bfloat162float(hz));
            __nv_bfloat16 lw = __float2bfloat16(v.w - __bfloat162float(hw));
            int off = r * PITCH + k0;
            *(uint2*)(sXhi + off) = make_uint2(packbf(hx, hy), packbf(hz, hw));
            *(uint2*)(sXlo + off) = make_uint2(packbf(lx, ly), packbf(lz, lw));
        }
        __syncthreads();

        float acc[8][4];
#pragma unroll
        for (int t = 0; t < 8; t++)
#pragma unroll
            for (int c = 0; c < 4; c++) acc[t][c] = 0.f;

#pragma unroll
        for (int ks = 0; ks < 8; ks++) {
            uint32_t ko2 = (uint32_t)(ks * 32);   // 16 bf16 cols = 32 bytes
            uint32_t ah[4], al[4];
            LDSM_X4(ah, aHb + ko2);
            LDSM_X4(al, aLb + ko2);
#pragma unroll
            for (int ntp = 0; ntp < 4; ntp++) {
                uint32_t bh[4], bl[4];
                LDSM_X4(bh, bHb[ntp] + ko2);
                LDSM_X4(bl, bLb[ntp] + ko2);
                mma16816(acc[2 * ntp + 0], ah, bh[0], bh[1]);
                mma16816(acc[2 * ntp + 0], ah, bl[0], bl[1]);
                mma16816(acc[2 * ntp + 0], al, bh[0], bh[1]);
                mma16816(acc[2 * ntp + 1], ah, bh[2], bh[3]);
                mma16816(acc[2 * ntp + 1], ah, bl[2], bl[3]);
                mma16816(acc[2 * ntp + 1], al, bh[2], bh[3]);
            }
        }

        // epilogue: scale by dinv[row], direct float2 stores
        {
            int qrow = lane >> 2;
            int qk   = (lane & 3) * 2;
            int r0 = row0 + wr * 16 + qrow;
            int r1 = r0 + 8;
            float dv0 = (r0 < n) ? g_dinv[r0] : 0.f;
            float dv1 = (r1 < n) ? g_dinv[r1] : 0.f;
            int colbase = wc * 64 + qk;
#pragma unroll
            for (int nt = 0; nt < 8; nt++) {
                int col = colbase + nt * 8;
                if (r0 < n)
                    *(float2*)(Hout + (size_t)r0 * D + col) =
                        make_float2(acc[nt][0] * dv0, acc[nt][1] * dv0);
                if (r1 < n)
                    *(float2*)(Hout + (size_t)r1 * D + col) =
                        make_float2(acc[nt][2] * dv1, acc[nt][3] * dv1);
            }
        }
    }
}

// ---------------- CSR scatter: out[d] = (hs[d] + sum_{s in N(d)} hs[s]) * dinv[d] + bias
template <int CLEANUP>
__global__ __launch_bounds__(256) void scatter_csr_kernel(
    const float* __restrict__ hs, float* __restrict__ out,
    const float* __restrict__ bias, int n)
{
    int node = (blockIdx.x * blockDim.x + threadIdx.x) >> 5;
    int lane = threadIdx.x & 31;
    if (node < n) {
        size_t base = (size_t)node * D + lane * 4;
        float4 acc = *(const float4*)(hs + base);   // self loop
        int start = g_rowptr[node];
        int cnt   = g_deg[node];
        int j = 0;
        for (; j + 4 <= cnt; j += 4) {
            int s0 = __ldg(&g_csr[start + j + 0]);
            int s1 = __ldg(&g_csr[start + j + 1]);
            int s2 = __ldg(&g_csr[start + j + 2]);
            int s3 = __ldg(&g_csr[start + j + 3]);
            float4 v0 = *(const float4*)(hs + (size_t)s0 * D + lane * 4);
            float4 v1 = *(const float4*)(hs + (size_t)s1 * D + lane * 4);
            float4 v2 = *(const float4*)(hs + (size_t)s2 * D + lane * 4);
            float4 v3 = *(const float4*)(hs + (size_t)s3 * D + lane * 4);
            acc.x += (v0.x + v1.x) + (v2.x + v3.x);
            acc.y += (v0.y + v1.y) + (v2.y + v3.y);
            acc.z += (v0.z + v1.z) + (v2.z + v3.z);
            acc.w += (v0.w + v1.w) + (v2.w + v3.w);
        }
        for (; j < cnt; j++) {
            int s = __ldg(&g_csr[start + j]);
            float4 v = *(const float4*)(hs + (size_t)s * D + lane * 4);
            acc.x += v.x; acc.y += v.y; acc.z += v.z; acc.w += v.w;
        }
        float dv = g_dinv[node];
        float4 bv = ((const float4*)bias)[lane];
        float4 o;
        o.x = fmaf(acc.x, dv, bv.x);
        o.y = fmaf(acc.y, dv, bv.y);
        o.z = fmaf(acc.z, dv, bv.z);
        o.w = fmaf(acc.w, dv, bv.w);
        *(float4*)(out + base) = o;

        if (CLEANUP && lane == 0) g_deg[node] = 0;
    }
    if (CLEANUP && blockIdx.x == 0) {
        if (threadIdx.x < 2 * D) g_bnsums[threadIdx.x] = 0.0f;
        if (threadIdx.x == 0) g_total = 0;
    }
}

// ---------------- BN statistics: per-feature sum & sum of squares ----------------
__global__ __launch_bounds__(512) void bnstat_kernel(const float* __restrict__ agg, int n) {
    int f = threadIdx.x & (D - 1);
    int g = threadIdx.x >> 7;
    int r0 = blockIdx.x * 512 + g;
    int rend = min(n, (int)(blockIdx.x * 512 + 512));
    float s = 0.f, s2 = 0.f;
    for (int r = r0; r < rend; r += 4) {
        float v = agg[(size_t)r * D + f];
        s += v;
        s2 = fmaf(v, v, s2);
    }
    atomicAdd(&g_bnsums[f], s);
    atomicAdd(&g_bnsums[D + f], s2);
}

extern "C" void kernel_launch(void* const* d_in, const int* in_sizes, int n_in,
                              void* d_out, int out_size)
{
    const float* x     = (const float*)d_in[0];
    const int*   ei    = (const int*)  d_in[1];
    const float* W1    = (const float*)d_in[2];
    const float* b1    = (const float*)d_in[3];
    const float* gamma = (const float*)d_in[4];
    const float* beta  = (const float*)d_in[5];
    const float* W2    = (const float*)d_in[6];
    const float* b2    = (const float*)d_in[7];
    float* out = (float*)d_out;

    int n = in_sizes[0] / D;
    int E = in_sizes[1] / 2;
    const int* src = ei;
    const int* dst = ei + E;
    float invN = 1.0f / (float)n;

    // dyn smem: W hi/lo (128*PITCH each) + X hi/lo (64*PITCH each), bf16
    int smem_mma = (2 * D * PITCH + 2 * 64 * PITCH) * 2;   // 104448 B
    cudaFuncSetAttribute(gemm_mma_kernel,
                         cudaFuncAttributeMaxDynamicSharedMemorySize, smem_mma);

    void* p;
    cudaGetSymbolAddress(&p, g_h);    float* hbuf   = (float*)p;
    cudaGetSymbolAddress(&p, g_agg);  float* aggbuf = (float*)p;
    cudaGetSymbolAddress(&p, g_w1hi); const __nv_bfloat16* w1hi = (const __nv_bfloat16*)p;
    cudaGetSymbolAddress(&p, g_w1lo); const __nv_bfloat16* w1lo = (const __nv_bfloat16*)p;
    cudaGetSymbolAddress(&p, g_w2hi); const __nv_bfloat16* w2hi = (const __nv_bfloat16*)p;
    cudaGetSymbolAddress(&p, g_w2lo); const __nv_bfloat16* w2lo = (const __nv_bfloat16*)p;

    int nb = (n + 255) / 256;
    int ntiles = (n + 63) / 64;
    int gblocks = ntiles < 296 ? ntiles : 296;   // 2 CTAs/SM, persistent
    int sblocks = (n * 32 + 255) / 256;
    int e4 = (E + 3) / 4;
    int pthreads = (e4 > 2 * D * D) ? e4 : 2 * D * D;

    // prep: fused W images + degree histogram, then offsets, then bucket fill
    prep_kernel<<<(pthreads + 255) / 256, 256>>>(dst, E, W1, W2);
    alloc_kernel<<<nb, 256>>>(n);
    fill_kernel<<<(e4 + 255) / 256, 256>>>(src, dst, E);

    // conv1
    gemm_mma_kernel<<<gblocks, 256, smem_mma>>>(x, w1hi, w1lo, hbuf, n, 0,
                                                nullptr, nullptr, invN);
    scatter_csr_kernel<0><<<sblocks, 256>>>(hbuf, aggbuf, b1, n);

    // BN stats over conv1 output
    bnstat_kernel<<<(n + 511) / 512, 512>>>(aggbuf, n);

    // conv2 (BN+ReLU fused into X staging; scratch cleanup fused into scatter2)
    gemm_mma_kernel<<<gblocks, 256, smem_mma>>>(aggbuf, w2hi, w2lo, hbuf, n, 1,
                                                gamma, beta, invN);
    scatter_csr_kernel<1><<<sblocks, 256>>>(hbuf, out, b2, n);
}

// round 10
// speedup vs baseline: 1.9745x; 1.1350x over previous
#include <cuda_runtime.h>
#include <cuda_bf16.h>
#include <cuda_fp16.h>
#include <cstdint>

#define D    128
#define MAXN 50048
#define MAXE 1000000
#define PITCH 136          // bf16 elements per smem row (conflict-free fragment LDS)

// ---- scratch (zero-initialized at module load; re-zeroed by scatter2 epilogue) ----
__device__ float g_dinv[MAXN];
__device__ int   g_deg[MAXN];       // must be 0 at start of every replay
__device__ int   g_rowptr[MAXN];
__device__ int   g_cursor[MAXN];
__device__ int   g_csr[MAXE];
__device__ __half g_h[(size_t)MAXN * D];   // fp16 intermediate h (halves gather traffic)
__device__ float g_agg[(size_t)MAXN * D];
__device__ float g_bnsums[2 * D];   // must be 0 at start of every replay
__device__ int   g_total;           // must be 0 at start of every replay
// bf16 hi/lo images of W^T, plain [n][k] row-major
__device__ __nv_bfloat16 g_w1hi[D * D], g_w1lo[D * D];
__device__ __nv_bfloat16 g_w2hi[D * D], g_w2lo[D * D];

__device__ __forceinline__ uint32_t packbf(__nv_bfloat16 a, __nv_bfloat16 b) {
    return (uint32_t)__bfloat16_as_ushort(a) | ((uint32_t)__bfloat16_as_ushort(b) << 16);
}

// warp mma: D(m16n8,f32) += A(m16k16,bf16) * B(k16n8,bf16)
__device__ __forceinline__ void mma16816(float* c, const uint32_t* a,
                                         uint32_t b0, uint32_t b1) {
    asm volatile(
        "mma.sync.aligned.m16n8k16.row.col.f32.bf16.bf16.f32 "
        "{%0,%1,%2,%3}, {%4,%5,%6,%7}, {%8,%9}, {%0,%1,%2,%3};"
        : "+f"(c[0]), "+f"(c[1]), "+f"(c[2]), "+f"(c[3])
        : "r"(a[0]), "r"(a[1]), "r"(a[2]), "r"(a[3]), "r"(b0), "r"(b1));
}
#define LDSM_X4(r, addr)                                                     \
    asm volatile("ldmatrix.sync.aligned.m8n8.x4.shared.b16 {%0,%1,%2,%3}, [%4];" \
        : "=r"((r)[0]), "=r"((r)[1]), "=r"((r)[2]), "=r"((r)[3]) : "r"(addr))

// load 4 consecutive halves as float4
__device__ __forceinline__ float4 ld4h(const __half* p) {
    uint2 raw = *(const uint2*)p;
    __half2 p0 = *reinterpret_cast<__half2*>(&raw.x);
    __half2 p1 = *reinterpret_cast<__half2*>(&raw.y);
    float2 f0 = __half22float2(p0);
    float2 f1 = __half22float2(p1);
    return make_float4(f0.x, f0.y, f1.x, f1.y);
}

// ---------------- fused prep: W images (bf16 hi/lo, Wt[n][k]) + degree histogram
__global__ void prep_kernel(const int* __restrict__ dst, int E,
                            const float* __restrict__ W1, const float* __restrict__ W2) {
    int i = blockIdx.x * blockDim.x + threadIdx.x;
    if (i < 2 * D * D) {
        int which = i >> 14;
        int e = i & 16383;
        float v = (which ? W2 : W1)[e];
        int k = e >> 7, nn = e & 127;                  // W[k][nn]
        __nv_bfloat16 hi = __float2bfloat16(v);
        __nv_bfloat16 lo = __float2bfloat16(v - __bfloat162float(hi));
        int off = nn * D + k;                          // Wt[n][k]
        if (which) { g_w2hi[off] = hi; g_w2lo[off] = lo; }
        else       { g_w1hi[off] = hi; g_w1lo[off] = lo; }
    }
    int base = i * 4;
    if (base + 3 < E) {
        int4 d = *(const int4*)(dst + base);
        atomicAdd(&g_deg[d.x], 1);
        atomicAdd(&g_deg[d.y], 1);
        atomicAdd(&g_deg[d.z], 1);
        atomicAdd(&g_deg[d.w], 1);
    } else {
        for (int u = base; u < E; u++) atomicAdd(&g_deg[dst[u]], 1);
    }
}

// ---------------- bucket allocation (order-free CSR offsets) + dinv ----------------
__global__ void alloc_kernel(int n) {
    int i = blockIdx.x * blockDim.x + threadIdx.x;
    if (i < n) {
        int dg = g_deg[i];
        int rp = atomicAdd(&g_total, dg);
        g_rowptr[i] = rp;
        g_cursor[i] = rp;
        g_dinv[i] = rsqrtf(1.0f + (float)dg);
    }
}

// ---------------- bucket fill: csr[dst buckets] = src (4 edges per thread) ----------------
__global__ void fill_kernel(const int* __restrict__ src, const int* __restrict__ dst, int E) {
    int i = blockIdx.x * blockDim.x + threadIdx.x;
    int base = i * 4;
    if (base + 3 < E) {
        int4 d = *(const int4*)(dst + base);
        int4 s = *(const int4*)(src + base);
        g_csr[atomicAdd(&g_cursor[d.x], 1)] = s.x;
        g_csr[atomicAdd(&g_cursor[d.y], 1)] = s.y;
        g_csr[atomicAdd(&g_cursor[d.z], 1)] = s.z;
        g_csr[atomicAdd(&g_cursor[d.w], 1)] = s.w;
    } else {
        for (int u = base; u < E; u++)
            g_csr[atomicAdd(&g_cursor[dst[u]], 1)] = src[u];
    }
}

// ---------------- HMMA GEMM: Hout(fp16) = (X @ W) * dinv[row]  (BN+ReLU on X if asked)
// bf16x3 emulated fp32: Ahi*Bhi + Ahi*Blo + Alo*Bhi. ldmatrix fragment loads.
// PERSISTENT: each CTA stages W once, then grid-strides over 64-row X tiles.
__global__ __launch_bounds__(256, 2) void gemm_mma_kernel(
    const float* __restrict__ X,
    const __nv_bfloat16* __restrict__ Wthi, const __nv_bfloat16* __restrict__ Wtlo,
    __half* __restrict__ Hout, int n, int use_bn,
    const float* __restrict__ gamma, const float* __restrict__ beta, float invN)
{
    extern __shared__ __align__(16) char sm[];
    __nv_bfloat16* sWhi = (__nv_bfloat16*)sm;                       // 128 x PITCH
    __nv_bfloat16* sWlo = sWhi + D * PITCH;
    __nv_bfloat16* sXhi = sWlo + D * PITCH;                         // 64 x PITCH
    __nv_bfloat16* sXlo = sXhi + 64 * PITCH;
    __shared__ float scale_s[D], shift_s[D];

    int tid  = threadIdx.x;
    int wid  = tid >> 5;
    int lane = tid & 31;

    if (use_bn && tid < D) {
        float mu  = g_bnsums[tid] * invN;
        float var = g_bnsums[D + tid] * invN - mu * mu;
        float sc  = gamma[tid] * rsqrtf(var + 1e-5f);
        scale_s[tid] = sc;
        shift_s[tid] = beta[tid] - mu * sc;
    }

    // stage W hi/lo ONCE: 2048 uint4 each; dst row pitch = 272 B (17 uint4)
    {
        const uint4* wh = (const uint4*)Wthi;
        const uint4* wl = (const uint4*)Wtlo;
#pragma unroll
        for (int i = 0; i < 8; i++) {
            int j = tid + i * 256;            // 0..2047
            int row = j >> 4, chunk = j & 15;
            *(uint4*)((char*)sWhi + row * (PITCH * 2) + chunk * 16) = wh[j];
            *(uint4*)((char*)sWlo + row * (PITCH * 2) + chunk * 16) = wl[j];
        }
    }

    int wr = wid & 3;        // row tile (m16)
    int wc = wid >> 2;       // col half (n64)

    // ldmatrix lane-address bases (byte offsets in shared space)
    uint32_t aRow = (uint32_t)(wr * 16 + (lane & 15));
    uint32_t aCol = (uint32_t)((lane >> 4) << 3);
    uint32_t aOff = (aRow * PITCH + aCol) * 2;
    uint32_t aHb = (uint32_t)__cvta_generic_to_shared(sXhi) + aOff;
    uint32_t aLb = (uint32_t)__cvta_generic_to_shared(sXlo) + aOff;
    uint32_t bRowL = (uint32_t)((lane & 7) + ((lane & 16) >> 1));
    uint32_t bColL = (uint32_t)(lane & 8);
    uint32_t bHb[4], bLb[4];
#pragma unroll
    for (int ntp = 0; ntp < 4; ntp++) {
        uint32_t row = (uint32_t)(wc * 64 + ntp * 16) + bRowL;
        uint32_t off = (row * PITCH + bColL) * 2;
        bHb[ntp] = (uint32_t)__cvta_generic_to_shared(sWhi) + off;
        bLb[ntp] = (uint32_t)__cvta_generic_to_shared(sWlo) + off;
    }

    int ntiles = (n + 63) >> 6;
    for (int tile = blockIdx.x; tile < ntiles; tile += gridDim.x) {
        __syncthreads();   // W/scale ready (1st iter); X smem free (later iters)

        // stage X hi/lo (64 rows), BN+ReLU fused
        int row0 = tile * 64;
#pragma unroll
        for (int i = 0; i < 8; i++) {
            int idx = tid + i * 256;              // 0..2047
            int r = idx >> 5, c4 = idx & 31, k0 = c4 * 4;
            int grow = row0 + r;
            float4 v = make_float4(0.f, 0.f, 0.f, 0.f);
            if (grow < n) v = ((const float4*)X)[(size_t)grow * 32 + c4];
            if (use_bn) {
                v.x = fmaxf(0.f, fmaf(v.x, scale_s[k0 + 0], shift_s[k0 + 0]));
                v.y = fmaxf(0.f, fmaf(v.y, scale_s[k0 + 1], shift_s[k0 + 1]));
                v.z = fmaxf(0.f, fmaf(v.z, scale_s[k0 + 2], shift_s[k0 + 2]));
                v.w = fmaxf(0.f, fmaf(v.w, scale_s[k0 + 3], shift_s[k0 + 3]));
            }
            __nv_bfloat16 hx = __float2bfloat16(v.x), hy = __float2bfloat16(v.y);
            __nv_bfloat16 hz = __float2bfloat16(v.z), hw = __float2bfloat16(v.w);
            __nv_bfloat16 lx = __float2bfloat16(v.x - __bfloat162float(hx));
            __nv_bfloat16 ly = __float2bfloat16(v.y - __bfloat162float(hy));
            __nv_bfloat16 lz = __float2bfloat16(v.z - __bfloat162float(hz));
            __nv_bfloat16 lw = __float2bfloat16(v.w - __bfloat162float(hw));
            int off = r * PITCH + k0;
            *(uint2*)(sXhi + off) = make_uint2(packbf(hx, hy), packbf(hz, hw));
            *(uint2*)(sXlo + off) = make_uint2(packbf(lx, ly), packbf(lz, lw));
        }
        __syncthreads();

        float acc[8][4];
#pragma unroll
        for (int t = 0; t < 8; t++)
#pragma unroll
            for (int c = 0; c < 4; c++) acc[t][c] = 0.f;

#pragma unroll
        for (int ks = 0; ks < 8; ks++) {
            uint32_t ko2 = (uint32_t)(ks * 32);   // 16 bf16 cols = 32 bytes
            uint32_t ah[4], al[4];
            LDSM_X4(ah, aHb + ko2);
            LDSM_X4(al, aLb + ko2);
#pragma unroll
            for (int ntp = 0; ntp < 4; ntp++) {
                uint32_t bh[4], bl[4];
                LDSM_X4(bh, bHb[ntp] + ko2);
                LDSM_X4(bl, bLb[ntp] + ko2);
                mma16816(acc[2 * ntp + 0], ah, bh[0], bh[1]);
                mma16816(acc[2 * ntp + 0], ah, bl[0], bl[1]);
                mma16816(acc[2 * ntp + 0], al, bh[0], bh[1]);
                mma16816(acc[2 * ntp + 1], ah, bh[2], bh[3]);
                mma16816(acc[2 * ntp + 1], ah, bl[2], bl[3]);
                mma16816(acc[2 * ntp + 1], al, bh[2], bh[3]);
            }
        }

        // epilogue: scale by dinv[row], fp16 stores (half2 per n-tile)
        {
            int qrow = lane >> 2;
            int qk   = (lane & 3) * 2;
            int r0 = row0 + wr * 16 + qrow;
            int r1 = r0 + 8;
            float dv0 = (r0 < n) ? g_dinv[r0] : 0.f;
            float dv1 = (r1 < n) ? g_dinv[r1] : 0.f;
            int colbase = wc * 64 + qk;
#pragma unroll
            for (int nt = 0; nt < 8; nt++) {
                int col = colbase + nt * 8;
                if (r0 < n)
                    *(__half2*)(Hout + (size_t)r0 * D + col) =
                        __floats2half2_rn(acc[nt][0] * dv0, acc[nt][1] * dv0);
                if (r1 < n)
                    *(__half2*)(Hout + (size_t)r1 * D + col) =
                        __floats2half2_rn(acc[nt][2] * dv1, acc[nt][3] * dv1);
            }
        }
    }
}

// ---------------- CSR scatter: out[d] = (hs[d] + sum_{s in N(d)} hs[s]) * dinv[d] + bias
// hs is fp16 (halves gather traffic); all accumulation fp32.
template <int CLEANUP>
__global__ __launch_bounds__(256) void scatter_csr_kernel(
    const __half* __restrict__ hs, float* __restrict__ out,
    const float* __restrict__ bias, int n)
{
    int node = (blockIdx.x * blockDim.x + threadIdx.x) >> 5;
    int lane = threadIdx.x & 31;
    if (node < n) {
        size_t basef = (size_t)node * D + lane * 4;
        float4 acc = ld4h(hs + basef);   // self loop
        int start = g_rowptr[node];
        int cnt   = g_deg[node];
        int j = 0;
        for (; j + 4 <= cnt; j += 4) {
            int s0 = __ldg(&g_csr[start + j + 0]);
            int s1 = __ldg(&g_csr[start + j + 1]);
            int s2 = __ldg(&g_csr[start + j + 2]);
            int s3 = __ldg(&g_csr[start + j + 3]);
            float4 v0 = ld4h(hs + (size_t)s0 * D + lane * 4);
            float4 v1 = ld4h(hs + (size_t)s1 * D + lane * 4);
            float4 v2 = ld4h(hs + (size_t)s2 * D + lane * 4);
            float4 v3 = ld4h(hs + (size_t)s3 * D + lane * 4);
            acc.x += (v0.x + v1.x) + (v2.x + v3.x);
            acc.y += (v0.y + v1.y) + (v2.y + v3.y);
            acc.z += (v0.z + v1.z) + (v2.z + v3.z);
            acc.w += (v0.w + v1.w) + (v2.w + v3.w);
        }
        for (; j < cnt; j++) {
            int s = __ldg(&g_csr[start + j]);
            float4 v = ld4h(hs + (size_t)s * D + lane * 4);
            acc.x += v.x; acc.y += v.y; acc.z += v.z; acc.w += v.w;
        }
        float dv = g_dinv[node];
        float4 bv = ((const float4*)bias)[lane];
        float4 o;
        o.x = fmaf(acc.x, dv, bv.x);
        o.y = fmaf(acc.y, dv, bv.y);
        o.z = fmaf(acc.z, dv, bv.z);
        o.w = fmaf(acc.w, dv, bv.w);
        *(float4*)(out + basef) = o;

        if (CLEANUP && lane == 0) g_deg[node] = 0;
    }
    if (CLEANUP && blockIdx.x == 0) {
        if (threadIdx.x < 2 * D) g_bnsums[threadIdx.x] = 0.0f;
        if (threadIdx.x == 0) g_total = 0;
    }
}

// ---------------- BN statistics: per-feature sum & sum of squares ----------------
__global__ __launch_bounds__(512) void bnstat_kernel(const float* __restrict__ agg, int n) {
    int f = threadIdx.x & (D - 1);
    int g = threadIdx.x >> 7;
    int r0 = blockIdx.x * 512 + g;
    int rend = min(n, (int)(blockIdx.x * 512 + 512));
    float s = 0.f, s2 = 0.f;
    for (int r = r0; r < rend; r += 4) {
        float v = agg[(size_t)r * D + f];
        s += v;
        s2 = fmaf(v, v, s2);
    }
    atomicAdd(&g_bnsums[f], s);
    atomicAdd(&g_bnsums[D + f], s2);
}

extern "C" void kernel_launch(void* const* d_in, const int* in_sizes, int n_in,
                              void* d_out, int out_size)
{
    const float* x     = (const float*)d_in[0];
    const int*   ei    = (const int*)  d_in[1];
    const float* W1    = (const float*)d_in[2];
    const float* b1    = (const float*)d_in[3];
    const float* gamma = (const float*)d_in[4];
    const float* beta  = (const float*)d_in[5];
    const float* W2    = (const float*)d_in[6];
    const float* b2    = (const float*)d_in[7];
    float* out = (float*)d_out;

    int n = in_sizes[0] / D;
    int E = in_sizes[1] / 2;
    const int* src = ei;
    const int* dst = ei + E;
    float invN = 1.0f / (float)n;

    // dyn smem: W hi/lo (128*PITCH each) + X hi/lo (64*PITCH each), bf16
    int smem_mma = (2 * D * PITCH + 2 * 64 * PITCH) * 2;   // 104448 B
    cudaFuncSetAttribute(gemm_mma_kernel,
                         cudaFuncAttributeMaxDynamicSharedMemorySize, smem_mma);

    void* p;
    cudaGetSymbolAddress(&p, g_h);    __half* hbuf  = (__half*)p;
    cudaGetSymbolAddress(&p, g_agg);  float* aggbuf = (float*)p;
    cudaGetSymbolAddress(&p, g_w1hi); const __nv_bfloat16* w1hi = (const __nv_bfloat16*)p;
    cudaGetSymbolAddress(&p, g_w1lo); const __nv_bfloat16* w1lo = (const __nv_bfloat16*)p;
    cudaGetSymbolAddress(&p, g_w2hi); const __nv_bfloat16* w2hi = (const __nv_bfloat16*)p;
    cudaGetSymbolAddress(&p, g_w2lo); const __nv_bfloat16* w2lo = (const __nv_bfloat16*)p;

    int nb = (n + 255) / 256;
    int ntiles = (n + 63) / 64;
    int gblocks = ntiles < 296 ? ntiles : 296;   // 2 CTAs/SM, persistent
    int sblocks = (n * 32 + 255) / 256;
    int e4 = (E + 3) / 4;
    int pthreads = (e4 > 2 * D * D) ? e4 : 2 * D * D;

    // prep: fused W images + degree histogram, then offsets, then bucket fill
    prep_kernel<<<(pthreads + 255) / 256, 256>>>(dst, E, W1, W2);
    alloc_kernel<<<nb, 256>>>(n);
    fill_kernel<<<(e4 + 255) / 256, 256>>>(src, dst, E);

    // conv1
    gemm_mma_kernel<<<gblocks, 256, smem_mma>>>(x, w1hi, w1lo, hbuf, n, 0,
                                                nullptr, nullptr, invN);
    scatter_csr_kernel<0><<<sblocks, 256>>>(hbuf, aggbuf, b1, n);

    // BN stats over conv1 output
    bnstat_kernel<<<(n + 511) / 512, 512>>>(aggbuf, n);

    // conv2 (BN+ReLU fused into X staging; scratch cleanup fused into scatter2)
    gemm_mma_kernel<<<gblocks, 256, smem_mma>>>(aggbuf, w2hi, w2lo, hbuf, n, 1,
                                                gamma, beta, invN);
    scatter_csr_kernel<1><<<sblocks, 256>>>(hbuf, out, b2, n);
}

// round 11
// speedup vs baseline: 2.2826x; 1.1561x over previous
#include <cuda_runtime.h>
#include <cuda_fp16.h>
#include <cstdint>

#define D    128
#define MAXN 50048
#define MAXE 1000000
#define PITCH 136          // fp16 elements per smem row (conflict-free ldmatrix)

// ---- scratch (zero-initialized at module load; re-zeroed by scatter2 epilogue) ----
__device__ float g_dinv[MAXN];
__device__ int   g_deg[MAXN];       // must be 0 at start of every replay
__device__ int   g_rowptr[MAXN];
__device__ int   g_cursor[MAXN];
__device__ int   g_csr[MAXE];
__device__ __half g_h[(size_t)MAXN * D];   // fp16 intermediate h
__device__ float g_agg[(size_t)MAXN * D];
__device__ float g_bnsums[2 * D];   // must be 0 at start of every replay
__device__ int   g_total;           // must be 0 at start of every replay
// fp16 images of W^T, plain [n][k] row-major
__device__ __half g_w1h[D * D], g_w2h[D * D];

// warp mma: D(m16n8,f32) += A(m16k16,f16) * B(k16n8,f16)
__device__ __forceinline__ void mma16816(float* c, const uint32_t* a,
                                         uint32_t b0, uint32_t b1) {
    asm volatile(
        "mma.sync.aligned.m16n8k16.row.col.f32.f16.f16.f32 "
        "{%0,%1,%2,%3}, {%4,%5,%6,%7}, {%8,%9}, {%0,%1,%2,%3};"
        : "+f"(c[0]), "+f"(c[1]), "+f"(c[2]), "+f"(c[3])
        : "r"(a[0]), "r"(a[1]), "r"(a[2]), "r"(a[3]), "r"(b0), "r"(b1));
}
#define LDSM_X4(r, addr)                                                     \
    asm volatile("ldmatrix.sync.aligned.m8n8.x4.shared.b16 {%0,%1,%2,%3}, [%4];" \
        : "=r"((r)[0]), "=r"((r)[1]), "=r"((r)[2]), "=r"((r)[3]) : "r"(addr))

// load 4 consecutive halves as float4
__device__ __forceinline__ float4 ld4h(const __half* p) {
    uint2 raw = *(const uint2*)p;
    __half2 p0 = *reinterpret_cast<__half2*>(&raw.x);
    __half2 p1 = *reinterpret_cast<__half2*>(&raw.y);
    float2 f0 = __half22float2(p0);
    float2 f1 = __half22float2(p1);
    return make_float4(f0.x, f0.y, f1.x, f1.y);
}

// ---------------- fused prep: W^T fp16 images + degree histogram ----------------
__global__ void prep_kernel(const int* __restrict__ dst, int E,
                            const float* __restrict__ W1, const float* __restrict__ W2) {
    int i = blockIdx.x * blockDim.x + threadIdx.x;
    if (i < 2 * D * D) {
        int which = i >> 14;
        int e = i & 16383;
        float v = (which ? W2 : W1)[e];
        int k = e >> 7, nn = e & 127;                  // W[k][nn]
        int off = nn * D + k;                          // Wt[n][k]
        if (which) g_w2h[off] = __float2half(v);
        else       g_w1h[off] = __float2half(v);
    }
    int base = i * 4;
    if (base + 3 < E) {
        int4 d = *(const int4*)(dst + base);
        atomicAdd(&g_deg[d.x], 1);
        atomicAdd(&g_deg[d.y], 1);
        atomicAdd(&g_deg[d.z], 1);
        atomicAdd(&g_deg[d.w], 1);
    } else {
        for (int u = base; u < E; u++) atomicAdd(&g_deg[dst[u]], 1);
    }
}

// ---------------- bucket allocation (order-free CSR offsets) + dinv ----------------
__global__ void alloc_kernel(int n) {
    int i = blockIdx.x * blockDim.x + threadIdx.x;
    if (i < n) {
        int dg = g_deg[i];
        int rp = atomicAdd(&g_total, dg);
        g_rowptr[i] = rp;
        g_cursor[i] = rp;
        g_dinv[i] = rsqrtf(1.0f + (float)dg);
    }
}

// ---------------- bucket fill: csr[dst buckets] = src (4 edges per thread) ----------------
__global__ void fill_kernel(const int* __restrict__ src, const int* __restrict__ dst, int E) {
    int i = blockIdx.x * blockDim.x + threadIdx.x;
    int base = i * 4;
    if (base + 3 < E) {
        int4 d = *(const int4*)(dst + base);
        int4 s = *(const int4*)(src + base);
        g_csr[atomicAdd(&g_cursor[d.x], 1)] = s.x;
        g_csr[atomicAdd(&g_cursor[d.y], 1)] = s.y;
        g_csr[atomicAdd(&g_cursor[d.z], 1)] = s.z;
        g_csr[atomicAdd(&g_cursor[d.w], 1)] = s.w;
    } else {
        for (int u = base; u < E; u++)
            g_csr[atomicAdd(&g_cursor[dst[u]], 1)] = src[u];
    }
}

// ---------------- HMMA GEMM: Hout(fp16) = (X @ W) * dinv[row]  (BN+ReLU on X if asked)
// Single-pass fp16 MMA. PERSISTENT: each CTA stages W once, grid-strides 64-row tiles.
// 8 warps = 4 row-tiles(m16) x 2 col-halves(n64) per tile. 3 CTAs/SM.
__global__ __launch_bounds__(256, 3) void gemm_mma_kernel(
    const float* __restrict__ X,
    const __half* __restrict__ Wt,
    __half* __restrict__ Hout, int n, int use_bn,
    const float* __restrict__ gamma, const float* __restrict__ beta, float invN)
{
    extern __shared__ __align__(16) char sm[];
    __half* sW = (__half*)sm;                        // 128 x PITCH
    __half* sX = sW + D * PITCH;                     // 64 x PITCH
    __shared__ float scale_s[D], shift_s[D];

    int tid  = threadIdx.x;
    int wid  = tid >> 5;
    int lane = tid & 31;

    if (use_bn && tid < D) {
        float mu  = g_bnsums[tid] * invN;
        float var = g_bnsums[D + tid] * invN - mu * mu;
        float sc  = gamma[tid] * rsqrtf(var + 1e-5f);
        scale_s[tid] = sc;
        shift_s[tid] = beta[tid] - mu * sc;
    }

    // stage W ONCE: 2048 uint4; dst row pitch = 272 B (17 uint4)
    {
        const uint4* wsrc = (const uint4*)Wt;
#pragma unroll
        for (int i = 0; i < 8; i++) {
            int j = tid + i * 256;            // 0..2047
            int row = j >> 4, chunk = j & 15;
            *(uint4*)((char*)sW + row * (PITCH * 2) + chunk * 16) = wsrc[j];
        }
    }

    int wr = wid & 3;        // row tile (m16)
    int wc = wid >> 2;       // col half (n64)

    // ldmatrix lane-address bases (byte offsets in shared space)
    uint32_t aRow = (uint32_t)(wr * 16 + (lane & 15));
    uint32_t aCol = (uint32_t)((lane >> 4) << 3);
    uint32_t aB = (uint32_t)__cvta_generic_to_shared(sX) + (aRow * PITCH + aCol) * 2;
    uint32_t bRowL = (uint32_t)((lane & 7) + ((lane & 16) >> 1));
    uint32_t bColL = (uint32_t)(lane & 8);
    uint32_t bB[4];
#pragma unroll
    for (int ntp = 0; ntp < 4; ntp++) {
        uint32_t row = (uint32_t)(wc * 64 + ntp * 16) + bRowL;
        bB[ntp] = (uint32_t)__cvta_generic_to_shared(sW) + (row * PITCH + bColL) * 2;
    }

    int ntiles = (n + 63) >> 6;
    for (int tile = blockIdx.x; tile < ntiles; tile += gridDim.x) {
        __syncthreads();   // W/scale ready (1st iter); X smem free (later iters)

        // stage X fp16 (64 rows), BN+ReLU fused
        int row0 = tile * 64;
#pragma unroll
        for (int i = 0; i < 8; i++) {
            int idx = tid + i * 256;              // 0..2047
            int r = idx >> 5, c4 = idx & 31, k0 = c4 * 4;
            int grow = row0 + r;
            float4 v = make_float4(0.f, 0.f, 0.f, 0.f);
            if (grow < n) v = ((const float4*)X)[(size_t)grow * 32 + c4];
            if (use_bn) {
                v.x = fmaxf(0.f, fmaf(v.x, scale_s[k0 + 0], shift_s[k0 + 0]));
                v.y = fmaxf(0.f, fmaf(v.y, scale_s[k0 + 1], shift_s[k0 + 1]));
                v.z = fmaxf(0.f, fmaf(v.z, scale_s[k0 + 2], shift_s[k0 + 2]));
                v.w = fmaxf(0.f, fmaf(v.w, scale_s[k0 + 3], shift_s[k0 + 3]));
            }
            __half2 h0 = __floats2half2_rn(v.x, v.y);
            __half2 h1 = __floats2half2_rn(v.z, v.w);
            *(uint2*)(sX + r * PITCH + k0) =
                make_uint2(*(uint32_t*)&h0, *(uint32_t*)&h1);
        }
        __syncthreads();

        float acc[8][4];
#pragma unroll
        for (int t = 0; t < 8; t++)
#pragma unroll
            for (int c = 0; c < 4; c++) acc[t][c] = 0.f;

#pragma unroll
        for (int ks = 0; ks < 8; ks++) {
            uint32_t ko2 = (uint32_t)(ks * 32);   // 16 fp16 cols = 32 bytes
            uint32_t a[4];
            LDSM_X4(a, aB + ko2);
#pragma unroll
            for (int ntp = 0; ntp < 4; ntp++) {
                uint32_t b[4];
                LDSM_X4(b, bB[ntp] + ko2);   // {b0,b1} of nt=2ntp, {b0,b1} of nt=2ntp+1
                mma16816(acc[2 * ntp + 0], a, b[0], b[1]);
                mma16816(acc[2 * ntp + 1], a, b[2], b[3]);
            }
        }

        // epilogue: scale by dinv[row], fp16 stores (half2 per n-tile)
        {
            int qrow = lane >> 2;
            int qk   = (lane & 3) * 2;
            int r0 = row0 + wr * 16 + qrow;
            int r1 = r0 + 8;
            float dv0 = (r0 < n) ? g_dinv[r0] : 0.f;
            float dv1 = (r1 < n) ? g_dinv[r1] : 0.f;
            int colbase = wc * 64 + qk;
#pragma unroll
            for (int nt = 0; nt < 8; nt++) {
                int col = colbase + nt * 8;
                if (r0 < n)
                    *(__half2*)(Hout + (size_t)r0 * D + col) =
                        __floats2half2_rn(acc[nt][0] * dv0, acc[nt][1] * dv0);
                if (r1 < n)
                    *(__half2*)(Hout + (size_t)r1 * D + col) =
                        __floats2half2_rn(acc[nt][2] * dv1, acc[nt][3] * dv1);
            }
        }
    }
}

// ---------------- CSR scatter: out[d] = (hs[d] + sum_{s in N(d)} hs[s]) * dinv[d] + bias
// hs is fp16; all accumulation fp32.
template <int CLEANUP>
__global__ __launch_bounds__(256) void scatter_csr_kernel(
    const __half* __restrict__ hs, float* __restrict__ out,
    const float* __restrict__ bias, int n)
{
    int node = (blockIdx.x * blockDim.x + threadIdx.x) >> 5;
    int lane = threadIdx.x & 31;
    if (node < n) {
        size_t basef = (size_t)node * D + lane * 4;
        float4 acc = ld4h(hs + basef);   // self loop
        int start = g_rowptr[node];
        int cnt   = g_deg[node];
        int j = 0;
        for (; j + 4 <= cnt; j += 4) {
            int s0 = __ldg(&g_csr[start + j + 0]);
            int s1 = __ldg(&g_csr[start + j + 1]);
            int s2 = __ldg(&g_csr[start + j + 2]);
            int s3 = __ldg(&g_csr[start + j + 3]);
            float4 v0 = ld4h(hs + (size_t)s0 * D + lane * 4);
            float4 v1 = ld4h(hs + (size_t)s1 * D + lane * 4);
            float4 v2 = ld4h(hs + (size_t)s2 * D + lane * 4);
            float4 v3 = ld4h(hs + (size_t)s3 * D + lane * 4);
            acc.x += (v0.x + v1.x) + (v2.x + v3.x);
            acc.y += (v0.y + v1.y) + (v2.y + v3.y);
            acc.z += (v0.z + v1.z) + (v2.z + v3.z);
            acc.w += (v0.w + v1.w) + (v2.w + v3.w);
        }
        for (; j < cnt; j++) {
            int s = __ldg(&g_csr[start + j]);
            float4 v = ld4h(hs + (size_t)s * D + lane * 4);
            acc.x += v.x; acc.y += v.y; acc.z += v.z; acc.w += v.w;
        }
        float dv = g_dinv[node];
        float4 bv = ((const float4*)bias)[lane];
        float4 o;
        o.x = fmaf(acc.x, dv, bv.x);
        o.y = fmaf(acc.y, dv, bv.y);
        o.z = fmaf(acc.z, dv, bv.z);
        o.w = fmaf(acc.w, dv, bv.w);
        *(float4*)(out + basef) = o;

        if (CLEANUP && lane == 0) g_deg[node] = 0;
    }
    if (CLEANUP && blockIdx.x == 0) {
        if (threadIdx.x < 2 * D) g_bnsums[threadIdx.x] = 0.0f;
        if (threadIdx.x == 0) g_total = 0;
    }
}

// ---------------- BN statistics: per-feature sum & sum of squares ----------------
__global__ __launch_bounds__(512) void bnstat_kernel(const float* __restrict__ agg, int n) {
    int f = threadIdx.x & (D - 1);
    int g = threadIdx.x >> 7;
    int r0 = blockIdx.x * 512 + g;
    int rend = min(n, (int)(blockIdx.x * 512 + 512));
    float s = 0.f, s2 = 0.f;
    for (int r = r0; r < rend; r += 4) {
        float v = agg[(size_t)r * D + f];
        s += v;
        s2 = fmaf(v, v, s2);
    }
    atomicAdd(&g_bnsums[f], s);
    atomicAdd(&g_bnsums[D + f], s2);
}

extern "C" void kernel_launch(void* const* d_in, const int* in_sizes, int n_in,
                              void* d_out, int out_size)
{
    const float* x     = (const float*)d_in[0];
    const int*   ei    = (const int*)  d_in[1];
    const float* W1    = (const float*)d_in[2];
    const float* b1    = (const float*)d_in[3];
    const float* gamma = (const float*)d_in[4];
    const float* beta  = (const float*)d_in[5];
    const float* W2    = (const float*)d_in[6];
    const float* b2    = (const float*)d_in[7];
    float* out = (float*)d_out;

    int n = in_sizes[0] / D;
    int E = in_sizes[1] / 2;
    const int* src = ei;
    const int* dst = ei + E;
    float invN = 1.0f / (float)n;

    // dyn smem: W (128*PITCH) + X (64*PITCH), fp16
    int smem_mma = (D * PITCH + 64 * PITCH) * 2;   // 52224 B
    cudaFuncSetAttribute(gemm_mma_kernel,
                         cudaFuncAttributeMaxDynamicSharedMemorySize, smem_mma);

    void* p;
    cudaGetSymbolAddress(&p, g_h);    __half* hbuf  = (__half*)p;
    cudaGetSymbolAddress(&p, g_agg);  float* aggbuf = (float*)p;
    cudaGetSymbolAddress(&p, g_w1h);  const __half* w1h = (const __half*)p;
    cudaGetSymbolAddress(&p, g_w2h);  const __half* w2h = (const __half*)p;

    int nb = (n + 255) / 256;
    int ntiles = (n + 63) / 64;
    int maxblocks = 148 * 3;                       // 3 CTAs/SM, persistent
    int gblocks = ntiles < maxblocks ? ntiles : maxblocks;
    int sblocks = (n * 32 + 255) / 256;
    int e4 = (E + 3) / 4;
    int pthreads = (e4 > 2 * D * D) ? e4 : 2 * D * D;

    // prep: fused W images + degree histogram, then offsets, then bucket fill
    prep_kernel<<<(pthreads + 255) / 256, 256>>>(dst, E, W1, W2);
    alloc_kernel<<<nb, 256>>>(n);
    fill_kernel<<<(e4 + 255) / 256, 256>>>(src, dst, E);

    // conv1
    gemm_mma_kernel<<<gblocks, 256, smem_mma>>>(x, w1h, hbuf, n, 0,
                                                nullptr, nullptr, invN);
    scatter_csr_kernel<0><<<sblocks, 256>>>(hbuf, aggbuf, b1, n);

    // BN stats over conv1 output
    bnstat_kernel<<<(n + 511) / 512, 512>>>(aggbuf, n);

    // conv2 (BN+ReLU fused into X staging; scratch cleanup fused into scatter2)
    gemm_mma_kernel<<<gblocks, 256, smem_mma>>>(aggbuf, w2h, hbuf, n, 1,
                                                gamma, beta, invN);
    scatter_csr_kernel<1><<<sblocks, 256>>>(hbuf, out, b2, n);
}

// round 12
// speedup vs baseline: 2.3337x; 1.0224x over previous
#include <cuda_runtime.h>
#include <cuda_fp16.h>
#include <cstdint>

#define D    128
#define MAXN 50048
#define MAXE 1000000
#define PITCH 136          // fp16 elements per smem row (conflict-free ldmatrix)

// ---- scratch (zero-initialized at module load; re-zeroed by scatter2 epilogue) ----
__device__ float g_dinv[MAXN];
__device__ int   g_deg[MAXN];       // must be 0 at start of every replay
__device__ int   g_rowptr[MAXN];
__device__ int   g_cursor[MAXN];
__device__ int   g_csr[MAXE];
__device__ __half g_h[(size_t)MAXN * D];    // fp16 intermediate h
__device__ __half g_agg[(size_t)MAXN * D];  // fp16 conv1 output / BN input
__device__ float g_bnsums[2 * D];   // must be 0 at start of every replay
__device__ int   g_total;           // must be 0 at start of every replay
// fp16 images of W^T, plain [n][k] row-major
__device__ __half g_w1h[D * D], g_w2h[D * D];

// warp mma: D(m16n8,f32) += A(m16k16,f16) * B(k16n8,f16)
__device__ __forceinline__ void mma16816(float* c, const uint32_t* a,
                                         uint32_t b0, uint32_t b1) {
    asm volatile(
        "mma.sync.aligned.m16n8k16.row.col.f32.f16.f16.f32 "
        "{%0,%1,%2,%3}, {%4,%5,%6,%7}, {%8,%9}, {%0,%1,%2,%3};"
        : "+f"(c[0]), "+f"(c[1]), "+f"(c[2]), "+f"(c[3])
        : "r"(a[0]), "r"(a[1]), "r"(a[2]), "r"(a[3]), "r"(b0), "r"(b1));
}
#define LDSM_X4(r, addr)                                                     \
    asm volatile("ldmatrix.sync.aligned.m8n8.x4.shared.b16 {%0,%1,%2,%3}, [%4];" \
        : "=r"((r)[0]), "=r"((r)[1]), "=r"((r)[2]), "=r"((r)[3]) : "r"(addr))

// load 4 consecutive halves as float4
__device__ __forceinline__ float4 ld4h(const __half* p) {
    uint2 raw = *(const uint2*)p;
    __half2 p0 = *reinterpret_cast<__half2*>(&raw.x);
    __half2 p1 = *reinterpret_cast<__half2*>(&raw.y);
    float2 f0 = __half22float2(p0);
    float2 f1 = __half22float2(p1);
    return make_float4(f0.x, f0.y, f1.x, f1.y);
}

// ---------------- fused prep: W^T fp16 images + degree histogram ----------------
__global__ void prep_kernel(const int* __restrict__ dst, int E,
                            const float* __restrict__ W1, const float* __restrict__ W2) {
    int i = blockIdx.x * blockDim.x + threadIdx.x;
    if (i < 2 * D * D) {
        int which = i >> 14;
        int e = i & 16383;
        float v = (which ? W2 : W1)[e];
        int k = e >> 7, nn = e & 127;                  // W[k][nn]
        int off = nn * D + k;                          // Wt[n][k]
        if (which) g_w2h[off] = __float2half(v);
        else       g_w1h[off] = __float2half(v);
    }
    int base = i * 4;
    if (base + 3 < E) {
        int4 d = *(const int4*)(dst + base);
        atomicAdd(&g_deg[d.x], 1);
        atomicAdd(&g_deg[d.y], 1);
        atomicAdd(&g_deg[d.z], 1);
        atomicAdd(&g_deg[d.w], 1);
    } else {
        for (int u = base; u < E; u++) atomicAdd(&g_deg[dst[u]], 1);
    }
}

// ---------------- bucket allocation (order-free CSR offsets) + dinv ----------------
__global__ void alloc_kernel(int n) {
    int i = blockIdx.x * blockDim.x + threadIdx.x;
    if (i < n) {
        int dg = g_deg[i];
        int rp = atomicAdd(&g_total, dg);
        g_rowptr[i] = rp;
        g_cursor[i] = rp;
        g_dinv[i] = rsqrtf(1.0f + (float)dg);
    }
}

// ---------------- bucket fill: csr[dst buckets] = src (4 edges per thread) ----------------
__global__ void fill_kernel(const int* __restrict__ src, const int* __restrict__ dst, int E) {
    int i = blockIdx.x * blockDim.x + threadIdx.x;
    int base = i * 4;
    if (base + 3 < E) {
        int4 d = *(const int4*)(dst + base);
        int4 s = *(const int4*)(src + base);
        g_csr[atomicAdd(&g_cursor[d.x], 1)] = s.x;
        g_csr[atomicAdd(&g_cursor[d.y], 1)] = s.y;
        g_csr[atomicAdd(&g_cursor[d.z], 1)] = s.z;
        g_csr[atomicAdd(&g_cursor[d.w], 1)] = s.w;
    } else {
        for (int u = base; u < E; u++)
            g_csr[atomicAdd(&g_cursor[dst[u]], 1)] = src[u];
    }
}

// ---------------- HMMA GEMM: Hout(fp16) = (X @ W) * dinv[row]  (BN+ReLU on X if asked)
// Single-pass fp16 MMA. PERSISTENT: each CTA stages W once, grid-strides 64-row tiles.
// XT = float (conv1) or __half (conv2, with BN+ReLU fused). 3 CTAs/SM.
template <typename XT, int USE_BN>
__global__ __launch_bounds__(256, 3) void gemm_mma_kernel(
    const XT* __restrict__ X,
    const __half* __restrict__ Wt,
    __half* __restrict__ Hout, int n,
    const float* __restrict__ gamma, const float* __restrict__ beta, float invN)
{
    extern __shared__ __align__(16) char sm[];
    __half* sW = (__half*)sm;                        // 128 x PITCH
    __half* sX = sW + D * PITCH;                     // 64 x PITCH
    __shared__ float scale_s[D], shift_s[D];

    int tid  = threadIdx.x;
    int wid  = tid >> 5;
    int lane = tid & 31;

    if (USE_BN && tid < D) {
        float mu  = g_bnsums[tid] * invN;
        float var = g_bnsums[D + tid] * invN - mu * mu;
        float sc  = gamma[tid] * rsqrtf(var + 1e-5f);
        scale_s[tid] = sc;
        shift_s[tid] = beta[tid] - mu * sc;
    }

    // stage W ONCE: 2048 uint4; dst row pitch = 272 B (17 uint4)
    {
        const uint4* wsrc = (const uint4*)Wt;
#pragma unroll
        for (int i = 0; i < 8; i++) {
            int j = tid + i * 256;            // 0..2047
            int row = j >> 4, chunk = j & 15;
            *(uint4*)((char*)sW + row * (PITCH * 2) + chunk * 16) = wsrc[j];
        }
    }

    int wr = wid & 3;        // row tile (m16)
    int wc = wid >> 2;       // col half (n64)

    // ldmatrix lane-address bases (byte offsets in shared space)
    uint32_t aRow = (uint32_t)(wr * 16 + (lane & 15));
    uint32_t aCol = (uint32_t)((lane >> 4) << 3);
    uint32_t aB = (uint32_t)__cvta_generic_to_shared(sX) + (aRow * PITCH + aCol) * 2;
    uint32_t bRowL = (uint32_t)((lane & 7) + ((lane & 16) >> 1));
    uint32_t bColL = (uint32_t)(lane & 8);
    uint32_t bB[4];
#pragma unroll
    for (int ntp = 0; ntp < 4; ntp++) {
        uint32_t row = (uint32_t)(wc * 64 + ntp * 16) + bRowL;
        bB[ntp] = (uint32_t)__cvta_generic_to_shared(sW) + (row * PITCH + bColL) * 2;
    }

    int ntiles = (n + 63) >> 6;
    for (int tile = blockIdx.x; tile < ntiles; tile += gridDim.x) {
        __syncthreads();   // W/scale ready (1st iter); X smem free (later iters)

        // stage X fp16 (64 rows), BN+ReLU fused for the fp16 path
        int row0 = tile * 64;
#pragma unroll
        for (int i = 0; i < 8; i++) {
            int idx = tid + i * 256;              // 0..2047
            int r = idx >> 5, c4 = idx & 31, k0 = c4 * 4;
            int grow = row0 + r;
            float4 v = make_float4(0.f, 0.f, 0.f, 0.f);
            if (grow < n) {
                if (sizeof(XT) == 4) {
                    v = ((const float4*)X)[(size_t)grow * 32 + c4];
                } else {
                    v = ld4h((const __half*)X + (size_t)grow * D + k0);
                }
            }
            if (USE_BN) {
                v.x = fmaxf(0.f, fmaf(v.x, scale_s[k0 + 0], shift_s[k0 + 0]));
                v.y = fmaxf(0.f, fmaf(v.y, scale_s[k0 + 1], shift_s[k0 + 1]));
                v.z = fmaxf(0.f, fmaf(v.z, scale_s[k0 + 2], shift_s[k0 + 2]));
                v.w = fmaxf(0.f, fmaf(v.w, scale_s[k0 + 3], shift_s[k0 + 3]));
            }
            __half2 h0 = __floats2half2_rn(v.x, v.y);
            __half2 h1 = __floats2half2_rn(v.z, v.w);
            *(uint2*)(sX + r * PITCH + k0) =
                make_uint2(*(uint32_t*)&h0, *(uint32_t*)&h1);
        }
        __syncthreads();

        float acc[8][4];
#pragma unroll
        for (int t = 0; t < 8; t++)
#pragma unroll
            for (int c = 0; c < 4; c++) acc[t][c] = 0.f;

#pragma unroll
        for (int ks = 0; ks < 8; ks++) {
            uint32_t ko2 = (uint32_t)(ks * 32);   // 16 fp16 cols = 32 bytes
            uint32_t a[4];
            LDSM_X4(a, aB + ko2);
#pragma unroll
            for (int ntp = 0; ntp < 4; ntp++) {
                uint32_t b[4];
                LDSM_X4(b, bB[ntp] + ko2);
                mma16816(acc[2 * ntp + 0], a, b[0], b[1]);
                mma16816(acc[2 * ntp + 1], a, b[2], b[3]);
            }
        }

        // epilogue: scale by dinv[row], fp16 stores (half2 per n-tile)
        {
            int qrow = lane >> 2;
            int qk   = (lane & 3) * 2;
            int r0 = row0 + wr * 16 + qrow;
            int r1 = r0 + 8;
            float dv0 = (r0 < n) ? g_dinv[r0] : 0.f;
            float dv1 = (r1 < n) ? g_dinv[r1] : 0.f;
            int colbase = wc * 64 + qk;
#pragma unroll
            for (int nt = 0; nt < 8; nt++) {
                int col = colbase + nt * 8;
                if (r0 < n)
                    *(__half2*)(Hout + (size_t)r0 * D + col) =
                        __floats2half2_rn(acc[nt][0] * dv0, acc[nt][1] * dv0);
                if (r1 < n)
                    *(__half2*)(Hout + (size_t)r1 * D + col) =
                        __floats2half2_rn(acc[nt][2] * dv1, acc[nt][3] * dv1);
            }
        }
    }
}

// ---------------- CSR scatter: out[d] = (hs[d] + sum_{s in N(d)} hs[s]) * dinv[d] + bias
// hs is fp16; accumulation fp32; output fp16 (scatter1) or fp32 (scatter2).
template <int CLEANUP, typename OutT>
__global__ __launch_bounds__(256) void scatter_csr_kernel(
    const __half* __restrict__ hs, OutT* __restrict__ out,
    const float* __restrict__ bias, int n)
{
    int node = (blockIdx.x * blockDim.x + threadIdx.x) >> 5;
    int lane = threadIdx.x & 31;
    if (node < n) {
        size_t basef = (size_t)node * D + lane * 4;
        float4 acc = ld4h(hs + basef);   // self loop
        int start = g_rowptr[node];
        int cnt   = g_deg[node];
        int j = 0;
        for (; j + 4 <= cnt; j += 4) {
            int s0 = __ldg(&g_csr[start + j + 0]);
            int s1 = __ldg(&g_csr[start + j + 1]);
            int s2 = __ldg(&g_csr[start + j + 2]);
            int s3 = __ldg(&g_csr[start + j + 3]);
            float4 v0 = ld4h(hs + (size_t)s0 * D + lane * 4);
            float4 v1 = ld4h(hs + (size_t)s1 * D + lane * 4);
            float4 v2 = ld4h(hs + (size_t)s2 * D + lane * 4);
            float4 v3 = ld4h(hs + (size_t)s3 * D + lane * 4);
            acc.x += (v0.x + v1.x) + (v2.x + v3.x);
            acc.y += (v0.y + v1.y) + (v2.y + v3.y);
            acc.z += (v0.z + v1.z) + (v2.z + v3.z);
            acc.w += (v0.w + v1.w) + (v2.w + v3.w);
        }
        for (; j < cnt; j++) {
            int s = __ldg(&g_csr[start + j]);
            float4 v = ld4h(hs + (size_t)s * D + lane * 4);
            acc.x += v.x; acc.y += v.y; acc.z += v.z; acc.w += v.w;
        }
        float dv = g_dinv[node];
        float4 bv = ((const float4*)bias)[lane];
        float4 o;
        o.x = fmaf(acc.x, dv, bv.x);
        o.y = fmaf(acc.y, dv, bv.y);
        o.z = fmaf(acc.z, dv, bv.z);
        o.w = fmaf(acc.w, dv, bv.w);
        if (sizeof(OutT) == 4) {
            *(float4*)((float*)out + basef) = o;
        } else {
            __half2 h0 = __floats2half2_rn(o.x, o.y);
            __half2 h1 = __floats2half2_rn(o.z, o.w);
            *(uint2*)((__half*)out + basef) =
                make_uint2(*(uint32_t*)&h0, *(uint32_t*)&h1);
        }

        if (CLEANUP && lane == 0) g_deg[node] = 0;
    }
    if (CLEANUP && blockIdx.x == 0) {
        if (threadIdx.x < 2 * D) g_bnsums[threadIdx.x] = 0.0f;
        if (threadIdx.x == 0) g_total = 0;
    }
}

// ---------------- BN statistics: per-feature sum & sum of squares (fp16 agg) ----------------
__global__ __launch_bounds__(512) void bnstat_kernel(const __half* __restrict__ agg, int n) {
    int f = threadIdx.x & (D - 1);
    int g = threadIdx.x >> 7;
    int r0 = blockIdx.x * 512 + g;
    int rend = min(n, (int)(blockIdx.x * 512 + 512));
    float s = 0.f, s2 = 0.f;
    for (int r = r0; r < rend; r += 4) {
        float v = __half2float(agg[(size_t)r * D + f]);
        s += v;
        s2 = fmaf(v, v, s2);
    }
    atomicAdd(&g_bnsums[f], s);
    atomicAdd(&g_bnsums[D + f], s2);
}

extern "C" void kernel_launch(void* const* d_in, const int* in_sizes, int n_in,
                              void* d_out, int out_size)
{
    const float* x     = (const float*)d_in[0];
    const int*   ei    = (const int*)  d_in[1];
    const float* W1    = (const float*)d_in[2];
    const float* b1    = (const float*)d_in[3];
    const float* gamma = (const float*)d_in[4];
    const float* beta  = (const float*)d_in[5];
    const float* W2    = (const float*)d_in[6];
    const float* b2    = (const float*)d_in[7];
    float* out = (float*)d_out;

    int n = in_sizes[0] / D;
    int E = in_sizes[1] / 2;
    const int* src = ei;
    const int* dst = ei + E;
    float invN = 1.0f / (float)n;

    // dyn smem: W (128*PITCH) + X (64*PITCH), fp16
    int smem_mma = (D * PITCH + 64 * PITCH) * 2;   // 52224 B
    cudaFuncSetAttribute(gemm_mma_kernel<float, 0>,
                         cudaFuncAttributeMaxDynamicSharedMemorySize, smem_mma);
    cudaFuncSetAttribute(gemm_mma_kernel<__half, 1>,
                         cudaFuncAttributeMaxDynamicSharedMemorySize, smem_mma);

    void* p;
    cudaGetSymbolAddress(&p, g_h);    __half* hbuf   = (__half*)p;
    cudaGetSymbolAddress(&p, g_agg);  __half* aggbuf = (__half*)p;
    cudaGetSymbolAddress(&p, g_w1h);  const __half* w1h = (const __half*)p;
    cudaGetSymbolAddress(&p, g_w2h);  const __half* w2h = (const __half*)p;

    int nb = (n + 255) / 256;
    int ntiles = (n + 63) / 64;
    int maxblocks = 148 * 3;                       // 3 CTAs/SM, persistent
    int gblocks = ntiles < maxblocks ? ntiles : maxblocks;
    int sblocks = (n * 32 + 255) / 256;
    int e4 = (E + 3) / 4;
    int pthreads = (e4 > 2 * D * D) ? e4 : 2 * D * D;

    // prep: fused W images + degree histogram, then offsets, then bucket fill
    prep_kernel<<<(pthreads + 255) / 256, 256>>>(dst, E, W1, W2);
    alloc_kernel<<<nb, 256>>>(n);
    fill_kernel<<<(e4 + 255) / 256, 256>>>(src, dst, E);

    // conv1
    gemm_mma_kernel<float, 0><<<gblocks, 256, smem_mma>>>(x, w1h, hbuf, n,
                                                          nullptr, nullptr, invN);
    scatter_csr_kernel<0, __half><<<sblocks, 256>>>(hbuf, aggbuf, b1, n);

    // BN stats over conv1 output (fp16)
    bnstat_kernel<<<(n + 511) / 512, 512>>>(aggbuf, n);

    // conv2 (BN+ReLU fused into X staging; scratch cleanup fused into scatter2)
    gemm_mma_kernel<__half, 1><<<gblocks, 256, smem_mma>>>(aggbuf, w2h, hbuf, n,
                                                           gamma, beta, invN);
    scatter_csr_kernel<1, float><<<sblocks, 256>>>(hbuf, out, b2, n);
}

// round 13
// speedup vs baseline: 2.3396x; 1.0025x over previous
#include <cuda_runtime.h>
#include <cuda_fp16.h>
#include <cstdint>

#define D    128
#define MAXN 50048
#define MAXE 1000000
#define PITCH 136          // fp16 elements per smem row (conflict-free ldmatrix)

// ---- scratch (zero-initialized at module load; re-zeroed by scatter2 epilogue) ----
__device__ float g_dinv[MAXN];
__device__ int   g_deg[MAXN];       // must be 0 at start of every replay
__device__ int   g_rowptr[MAXN];
__device__ int   g_cursor[MAXN];
__device__ unsigned short g_csr[MAXE];      // u16 neighbor indices (N < 65536)
__device__ __half g_h[(size_t)MAXN * D];    // fp16 intermediate h
__device__ __half g_agg[(size_t)MAXN * D];  // fp16 conv1 output / BN input
__device__ float g_bnsums[2 * D];   // must be 0 at start of every replay
__device__ int   g_total;           // must be 0 at start of every replay
// fp16 images of W^T, plain [n][k] row-major
__device__ __half g_w1h[D * D], g_w2h[D * D];

// warp mma: D(m16n8,f32) += A(m16k16,f16) * B(k16n8,f16)
__device__ __forceinline__ void mma16816(float* c, const uint32_t* a,
                                         uint32_t b0, uint32_t b1) {
    asm volatile(
        "mma.sync.aligned.m16n8k16.row.col.f32.f16.f16.f32 "
        "{%0,%1,%2,%3}, {%4,%5,%6,%7}, {%8,%9}, {%0,%1,%2,%3};"
        : "+f"(c[0]), "+f"(c[1]), "+f"(c[2]), "+f"(c[3])
        : "r"(a[0]), "r"(a[1]), "r"(a[2]), "r"(a[3]), "r"(b0), "r"(b1));
}
#define LDSM_X4(r, addr)                                                     \
    asm volatile("ldmatrix.sync.aligned.m8n8.x4.shared.b16 {%0,%1,%2,%3}, [%4];" \
        : "=r"((r)[0]), "=r"((r)[1]), "=r"((r)[2]), "=r"((r)[3]) : "r"(addr))

// load 4 consecutive halves as float4
__device__ __forceinline__ float4 ld4h(const __half* p) {
    uint2 raw = *(const uint2*)p;
    __half2 p0 = *reinterpret_cast<__half2*>(&raw.x);
    __half2 p1 = *reinterpret_cast<__half2*>(&raw.y);
    float2 f0 = __half22float2(p0);
    float2 f1 = __half22float2(p1);
    return make_float4(f0.x, f0.y, f1.x, f1.y);
}
__device__ __forceinline__ float4 unpk2h(uint2 raw) {
    __half2 p0 = *reinterpret_cast<__half2*>(&raw.x);
    __half2 p1 = *reinterpret_cast<__half2*>(&raw.y);
    float2 f0 = __half22float2(p0);
    float2 f1 = __half22float2(p1);
    return make_float4(f0.x, f0.y, f1.x, f1.y);
}

// ---------------- fused prep: W^T fp16 images + degree histogram ----------------
__global__ void prep_kernel(const int* __restrict__ dst, int E,
                            const float* __restrict__ W1, const float* __restrict__ W2) {
    int i = blockIdx.x * blockDim.x + threadIdx.x;
    if (i < 2 * D * D) {
        int which = i >> 14;
        int e = i & 16383;
        float v = (which ? W2 : W1)[e];
        int k = e >> 7, nn = e & 127;                  // W[k][nn]
        int off = nn * D + k;                          // Wt[n][k]
        if (which) g_w2h[off] = __float2half(v);
        else       g_w1h[off] = __float2half(v);
    }
    int base = i * 4;
    if (base + 3 < E) {
        int4 d = *(const int4*)(dst + base);
        atomicAdd(&g_deg[d.x], 1);
        atomicAdd(&g_deg[d.y], 1);
        atomicAdd(&g_deg[d.z], 1);
        atomicAdd(&g_deg[d.w], 1);
    } else {
        for (int u = base; u < E; u++) atomicAdd(&g_deg[dst[u]], 1);
    }
}

// ---------------- bucket allocation (order-free CSR offsets) + dinv ----------------
__global__ void alloc_kernel(int n) {
    int i = blockIdx.x * blockDim.x + threadIdx.x;
    if (i < n) {
        int dg = g_deg[i];
        int rp = atomicAdd(&g_total, dg);
        g_rowptr[i] = rp;
        g_cursor[i] = rp;
        g_dinv[i] = rsqrtf(1.0f + (float)dg);
    }
}

// ---------------- bucket fill: csr[dst buckets] = src (4 edges per thread) ----------------
__global__ void fill_kernel(const int* __restrict__ src, const int* __restrict__ dst, int E) {
    int i = blockIdx.x * blockDim.x + threadIdx.x;
    int base = i * 4;
    if (base + 3 < E) {
        int4 d = *(const int4*)(dst + base);
        int4 s = *(const int4*)(src + base);
        g_csr[atomicAdd(&g_cursor[d.x], 1)] = (unsigned short)s.x;
        g_csr[atomicAdd(&g_cursor[d.y], 1)] = (unsigned short)s.y;
        g_csr[atomicAdd(&g_cursor[d.z], 1)] = (unsigned short)s.z;
        g_csr[atomicAdd(&g_cursor[d.w], 1)] = (unsigned short)s.w;
    } else {
        for (int u = base; u < E; u++)
            g_csr[atomicAdd(&g_cursor[dst[u]], 1)] = (unsigned short)src[u];
    }
}

// ---------------- HMMA GEMM: Hout(fp16) = (X @ W) * dinv[row]  (BN+ReLU on X if asked)
// Single-pass fp16 MMA, PERSISTENT with REGISTER PREFETCH: while the MMA of tile t
// runs, each thread already holds tile t+1's X values in registers.
// XT = float (conv1) or __half (conv2, BN+ReLU fused). 2 CTAs/SM.
template <typename XT, int USE_BN>
__global__ __launch_bounds__(256, 2) void gemm_mma_kernel(
    const XT* __restrict__ X,
    const __half* __restrict__ Wt,
    __half* __restrict__ Hout, int n,
    const float* __restrict__ gamma, const float* __restrict__ beta, float invN)
{
    extern __shared__ __align__(16) char sm[];
    __half* sW = (__half*)sm;                        // 128 x PITCH
    __half* sX = sW + D * PITCH;                     // 64 x PITCH
    __shared__ float scale_s[D], shift_s[D];

    int tid  = threadIdx.x;
    int wid  = tid >> 5;
    int lane = tid & 31;

    if (USE_BN && tid < D) {
        float mu  = g_bnsums[tid] * invN;
        float var = g_bnsums[D + tid] * invN - mu * mu;
        float sc  = gamma[tid] * rsqrtf(var + 1e-5f);
        scale_s[tid] = sc;
        shift_s[tid] = beta[tid] - mu * sc;
    }

    // stage W ONCE: 2048 uint4; dst row pitch = 272 B (17 uint4)
    {
        const uint4* wsrc = (const uint4*)Wt;
#pragma unroll
        for (int i = 0; i < 8; i++) {
            int j = tid + i * 256;            // 0..2047
            int row = j >> 4, chunk = j & 15;
            *(uint4*)((char*)sW + row * (PITCH * 2) + chunk * 16) = wsrc[j];
        }
    }

    int wr = wid & 3;        // row tile (m16)
    int wc = wid >> 2;       // col half (n64)

    // ldmatrix lane-address bases (byte offsets in shared space)
    uint32_t aRow = (uint32_t)(wr * 16 + (lane & 15));
    uint32_t aCol = (uint32_t)((lane >> 4) << 3);
    uint32_t aB = (uint32_t)__cvta_generic_to_shared(sX) + (aRow * PITCH + aCol) * 2;
    uint32_t bRowL = (uint32_t)((lane & 7) + ((lane & 16) >> 1));
    uint32_t bColL = (uint32_t)(lane & 8);
    uint32_t bB[4];
#pragma unroll
    for (int ntp = 0; ntp < 4; ntp++) {
        uint32_t row = (uint32_t)(wc * 64 + ntp * 16) + bRowL;
        bB[ntp] = (uint32_t)__cvta_generic_to_shared(sW) + (row * PITCH + bColL) * 2;
    }

    int ntiles = (n + 63) >> 6;

    // per-thread staging coordinates (fixed across tiles)
    int sr = tid >> 5;            // row within tile covered at i=0 step 8... (see loop)
    (void)sr;

    // prefetch registers: one of these is dead per instantiation
    float4 pf32[8];
    uint2  pf16[8];

    // prefetch X for a tile into registers (predicated; zeros out of range)
    auto prefetch = [&](int tile) {
#pragma unroll
        for (int i = 0; i < 8; i++) {
            int idx = tid + i * 256;              // 0..2047
            int r = idx >> 5, c4 = idx & 31;
            int grow = tile * 64 + r;
            bool ok = (tile < ntiles) && (grow < n);
            if (sizeof(XT) == 4) {
                pf32[i] = ok ? ((const float4*)X)[(size_t)grow * 32 + c4]
                             : make_float4(0.f, 0.f, 0.f, 0.f);
            } else {
                pf16[i] = ok ? *(const uint2*)((const __half*)X + (size_t)grow * D + c4 * 4)
                             : make_uint2(0u, 0u);
            }
        }
    };

    prefetch(blockIdx.x);

    for (int tile = blockIdx.x; tile < ntiles; tile += gridDim.x) {
        __syncthreads();   // W/scale ready (1st iter); sX consumed (later iters)

        // store prefetched X (BN+ReLU fused) to sX as fp16
#pragma unroll
        for (int i = 0; i < 8; i++) {
            int idx = tid + i * 256;
            int r = idx >> 5, c4 = idx & 31, k0 = c4 * 4;
            float4 v = (sizeof(XT) == 4) ? pf32[i] : unpk2h(pf16[i]);
            if (USE_BN) {
                v.x = fmaxf(0.f, fmaf(v.x, scale_s[k0 + 0], shift_s[k0 + 0]));
                v.y = fmaxf(0.f, fmaf(v.y, scale_s[k0 + 1], shift_s[k0 + 1]));
                v.z = fmaxf(0.f, fmaf(v.z, scale_s[k0 + 2], shift_s[k0 + 2]));
                v.w = fmaxf(0.f, fmaf(v.w, scale_s[k0 + 3], shift_s[k0 + 3]));
            }
            __half2 h0 = __floats2half2_rn(v.x, v.y);
            __half2 h1 = __floats2half2_rn(v.z, v.w);
            *(uint2*)(sX + r * PITCH + k0) =
                make_uint2(*(uint32_t*)&h0, *(uint32_t*)&h1);
        }

        // issue next tile's loads now; latency overlaps MMA + epilogue
        prefetch(tile + gridDim.x);

        __syncthreads();

        float acc[8][4];
#pragma unroll
        for (int t = 0; t < 8; t++)
#pragma unroll
            for (int c = 0; c < 4; c++) acc[t][c] = 0.f;

#pragma unroll
        for (int ks = 0; ks < 8; ks++) {
            uint32_t ko2 = (uint32_t)(ks * 32);   // 16 fp16 cols = 32 bytes
            uint32_t a[4];
            LDSM_X4(a, aB + ko2);
#pragma unroll
            for (int ntp = 0; ntp < 4; ntp++) {
                uint32_t b[4];
                LDSM_X4(b, bB[ntp] + ko2);
                mma16816(acc[2 * ntp + 0], a, b[0], b[1]);
                mma16816(acc[2 * ntp + 1], a, b[2], b[3]);
            }
        }

        // epilogue: scale by dinv[row], fp16 stores (half2 per n-tile)
        {
            int row0 = tile * 64;
            int qrow = lane >> 2;
            int qk   = (lane & 3) * 2;
            int r0 = row0 + wr * 16 + qrow;
            int r1 = r0 + 8;
            float dv0 = (r0 < n) ? g_dinv[r0] : 0.f;
            float dv1 = (r1 < n) ? g_dinv[r1] : 0.f;
            int colbase = wc * 64 + qk;
#pragma unroll
            for (int nt = 0; nt < 8; nt++) {
                int col = colbase + nt * 8;
                if (r0 < n)
                    *(__half2*)(Hout + (size_t)r0 * D + col) =
                        __floats2half2_rn(acc[nt][0] * dv0, acc[nt][1] * dv0);
                if (r1 < n)
                    *(__half2*)(Hout + (size_t)r1 * D + col) =
                        __floats2half2_rn(acc[nt][2] * dv1, acc[nt][3] * dv1);
            }
        }
    }
}

// ---------------- CSR scatter: out[d] = (hs[d] + sum_{s in N(d)} hs[s]) * dinv[d] + bias
// hs is fp16; accumulation fp32; output fp16 (scatter1) or fp32 (scatter2).
template <int CLEANUP, typename OutT>
__global__ __launch_bounds__(256) void scatter_csr_kernel(
    const __half* __restrict__ hs, OutT* __restrict__ out,
    const float* __restrict__ bias, int n)
{
    int node = (blockIdx.x * blockDim.x + threadIdx.x) >> 5;
    int lane = threadIdx.x & 31;
    if (node < n) {
        size_t basef = (size_t)node * D + lane * 4;
        float4 acc = ld4h(hs + basef);   // self loop
        int start = g_rowptr[node];
        int cnt   = g_deg[node];
        int j = 0;
        for (; j + 4 <= cnt; j += 4) {
            int s0 = (int)__ldg(&g_csr[start + j + 0]);
            int s1 = (int)__ldg(&g_csr[start + j + 1]);
            int s2 = (int)__ldg(&g_csr[start + j + 2]);
            int s3 = (int)__ldg(&g_csr[start + j + 3]);
            float4 v0 = ld4h(hs + (size_t)s0 * D + lane * 4);
            float4 v1 = ld4h(hs + (size_t)s1 * D + lane * 4);
            float4 v2 = ld4h(hs + (size_t)s2 * D + lane * 4);
            float4 v3 = ld4h(hs + (size_t)s3 * D + lane * 4);
            acc.x += (v0.x + v1.x) + (v2.x + v3.x);
            acc.y += (v0.y + v1.y) + (v2.y + v3.y);
            acc.z += (v0.z + v1.z) + (v2.z + v3.z);
            acc.w += (v0.w + v1.w) + (v2.w + v3.w);
        }
        for (; j < cnt; j++) {
            int s = (int)__ldg(&g_csr[start + j]);
            float4 v = ld4h(hs + (size_t)s * D + lane * 4);
            acc.x += v.x; acc.y += v.y; acc.z += v.z; acc.w += v.w;
        }
        float dv = g_dinv[node];
        float4 bv = ((const float4*)bias)[lane];
        float4 o;
        o.x = fmaf(acc.x, dv, bv.x);
        o.y = fmaf(acc.y, dv, bv.y);
        o.z = fmaf(acc.z, dv, bv.z);
        o.w = fmaf(acc.w, dv, bv.w);
        if (sizeof(OutT) == 4) {
            *(float4*)((float*)out + basef) = o;
        } else {
            __half2 h0 = __floats2half2_rn(o.x, o.y);
            __half2 h1 = __floats2half2_rn(o.z, o.w);
            *(uint2*)((__half*)out + basef) =
                make_uint2(*(uint32_t*)&h0, *(uint32_t*)&h1);
        }

        if (CLEANUP && lane == 0) g_deg[node] = 0;
    }
    if (CLEANUP && blockIdx.x == 0) {
        if (threadIdx.x < 2 * D) g_bnsums[threadIdx.x] = 0.0f;
        if (threadIdx.x == 0) g_total = 0;
    }
}

// ---------------- BN statistics: per-feature sum & sum of squares (fp16 agg) ----------------
__global__ __launch_bounds__(512) void bnstat_kernel(const __half* __restrict__ agg, int n) {
    int f = threadIdx.x & (D - 1);
    int g = threadIdx.x >> 7;
    int r0 = blockIdx.x * 512 + g;
    int rend = min(n, (int)(blockIdx.x * 512 + 512));
    float s = 0.f, s2 = 0.f;
    for (int r = r0; r < rend; r += 4) {
        float v = __half2float(agg[(size_t)r * D + f]);
        s += v;
        s2 = fmaf(v, v, s2);
    }
    atomicAdd(&g_bnsums[f], s);
    atomicAdd(&g_bnsums[D + f], s2);
}

extern "C" void kernel_launch(void* const* d_in, const int* in_sizes, int n_in,
                              void* d_out, int out_size)
{
    const float* x     = (const float*)d_in[0];
    const int*   ei    = (const int*)  d_in[1];
    const float* W1    = (const float*)d_in[2];
    const float* b1    = (const float*)d_in[3];
    const float* gamma = (const float*)d_in[4];
    const float* beta  = (const float*)d_in[5];
    const float* W2    = (const float*)d_in[6];
    const float* b2    = (const float*)d_in[7];
    float* out = (float*)d_out;

    int n = in_sizes[0] / D;
    int E = in_sizes[1] / 2;
    const int* src = ei;
    const int* dst = ei + E;
    float invN = 1.0f / (float)n;

    // dyn smem: W (128*PITCH) + X (64*PITCH), fp16
    int smem_mma = (D * PITCH + 64 * PITCH) * 2;   // 52224 B
    cudaFuncSetAttribute(gemm_mma_kernel<float, 0>,
                         cudaFuncAttributeMaxDynamicSharedMemorySize, smem_mma);
    cudaFuncSetAttribute(gemm_mma_kernel<__half, 1>,
                         cudaFuncAttributeMaxDynamicSharedMemorySize, smem_mma);

    void* p;
    cudaGetSymbolAddress(&p, g_h);    __half* hbuf   = (__half*)p;
    cudaGetSymbolAddress(&p, g_agg);  __half* aggbuf = (__half*)p;
    cudaGetSymbolAddress(&p, g_w1h);  const __half* w1h = (const __half*)p;
    cudaGetSymbolAddress(&p, g_w2h);  const __half* w2h = (const __half*)p;

    int nb = (n + 255) / 256;
    int ntiles = (n + 63) / 64;
    int maxblocks = 148 * 2;                       // 2 CTAs/SM, persistent
    int gblocks = ntiles < maxblocks ? ntiles : maxblocks;
    int sblocks = (n * 32 + 255) / 256;
    int e4 = (E + 3) / 4;
    int pthreads = (e4 > 2 * D * D) ? e4 : 2 * D * D;

    // prep: fused W images + degree histogram, then offsets, then bucket fill
    prep_kernel<<<(pthreads + 255) / 256, 256>>>(dst, E, W1, W2);
    alloc_kernel<<<nb, 256>>>(n);
    fill_kernel<<<(e4 + 255) / 256, 256>>>(src, dst, E);

    // conv1
    gemm_mma_kernel<float, 0><<<gblocks, 256, smem_mma>>>(x, w1h, hbuf, n,
                                                          nullptr, nullptr, invN);
    scatter_csr_kernel<0, __half><<<sblocks, 256>>>(hbuf, aggbuf, b1, n);

    // BN stats over conv1 output (fp16)
    bnstat_kernel<<<(n + 511) / 512, 512>>>(aggbuf, n);

    // conv2 (BN+ReLU fused into X staging; scratch cleanup fused into scatter2)
    gemm_mma_kernel<__half, 1><<<gblocks, 256, smem_mma>>>(aggbuf, w2h, hbuf, n,
                                                           gamma, beta, invN);
    scatter_csr_kernel<1, float><<<sblocks, 256>>>(hbuf, out, b2, n);
}